// round 1
// baseline (speedup 1.0000x reference)
#include <cuda_runtime.h>
#include <cstdint>
#include <math.h>

#define Bsz 32
#define Tsz 512
#define DIsz 512
#define Hsz 512
#define G4 2048
#define G5 2560
#define NCTA 148
#define NTHR 512
#define BTHn ((size_t)32*512*512)

// -------- static device scratch (alloc-free rule) --------
static __device__ float g_h[(size_t)4*512*32*512];       // h per layer,t,b,j
static __device__ float g_c[(size_t)4*512*32*512];       // c per layer,t,b,j
static __device__ float g_xproj[(size_t)512*32*2048];    // x@w_ih.T + bias, (t,b,4H)
static __device__ unsigned g_bar;

__device__ __forceinline__ float sigf(float x) { return 1.0f / (1.0f + __expf(-x)); }

__global__ void k_init() { g_bar = 0u; }

// ---------------- xproj = x @ w_ih.T + (b_ih + b_hh) ----------------
// M = T*B = 16384 (row m -> t = m>>5, b = m&31), N = 2048, K = 512
__global__ void __launch_bounds__(256) k_xproj(
    const float* __restrict__ x, const float* __restrict__ w_ih,
    const float* __restrict__ b_ih, const float* __restrict__ b_hh)
{
    __shared__ float As[16][65];
    __shared__ float Bs[16][65];
    const int bm = blockIdx.y * 64;
    const int bn = blockIdx.x * 64;
    const int tid = threadIdx.x;
    const int tr = (tid >> 4) << 2;
    const int tc = (tid & 15) << 2;
    float acc[4][4] = {};
    for (int k0 = 0; k0 < DIsz; k0 += 16) {
        #pragma unroll
        for (int i0 = 0; i0 < 4; i0++) {
            int i  = i0 * 256 + tid;
            int mm = i >> 4, kk = i & 15;
            int m  = bm + mm;
            int tt = m >> 5, bb = m & 31;
            As[kk][mm] = x[((size_t)bb * Tsz + tt) * DIsz + (k0 + kk)];
            Bs[kk][mm] = w_ih[(size_t)(bn + mm) * DIsz + (k0 + kk)];
        }
        __syncthreads();
        #pragma unroll
        for (int kk = 0; kk < 16; kk++) {
            float a0 = As[kk][tr+0], a1 = As[kk][tr+1], a2 = As[kk][tr+2], a3 = As[kk][tr+3];
            float b0 = Bs[kk][tc+0], b1 = Bs[kk][tc+1], b2 = Bs[kk][tc+2], b3 = Bs[kk][tc+3];
            acc[0][0] = fmaf(a0,b0,acc[0][0]); acc[0][1] = fmaf(a0,b1,acc[0][1]);
            acc[0][2] = fmaf(a0,b2,acc[0][2]); acc[0][3] = fmaf(a0,b3,acc[0][3]);
            acc[1][0] = fmaf(a1,b0,acc[1][0]); acc[1][1] = fmaf(a1,b1,acc[1][1]);
            acc[1][2] = fmaf(a1,b2,acc[1][2]); acc[1][3] = fmaf(a1,b3,acc[1][3]);
            acc[2][0] = fmaf(a2,b0,acc[2][0]); acc[2][1] = fmaf(a2,b1,acc[2][1]);
            acc[2][2] = fmaf(a2,b2,acc[2][2]); acc[2][3] = fmaf(a2,b3,acc[2][3]);
            acc[3][0] = fmaf(a3,b0,acc[3][0]); acc[3][1] = fmaf(a3,b1,acc[3][1]);
            acc[3][2] = fmaf(a3,b2,acc[3][2]); acc[3][3] = fmaf(a3,b3,acc[3][3]);
        }
        __syncthreads();
    }
    #pragma unroll
    for (int i = 0; i < 4; i++) {
        #pragma unroll
        for (int j = 0; j < 4; j++) {
            int n = bn + tc + j;
            g_xproj[(size_t)(bm + tr + i) * G4 + n] = acc[i][j] + b_ih[n] + b_hh[n];
        }
    }
}

// ---------------- persistent wavefront LSTM ----------------
// CTA 0..15   : layer 0 (plain LSTM), 32 j each, K=512 (recurrent only; input precomputed)
// CTA 16..147 : 44 CTAs per CALSTM layer 1..3, j-slices of 12/11, K=1024 over [h_low, h_prev]
__global__ void __launch_bounds__(NTHR, 1) k_wave(
    const float* __restrict__ w_hh, const float* __restrict__ ca_w,
    const float* __restrict__ ca_b, float* __restrict__ out)
{
    extern __shared__ float sm[];
    float* hx = sm;                 // [k*33 + b], k < 1024
    float* ms = sm + 1024 * 33;     // [c*32 + b], c < 128

    const int tid  = threadIdx.x;
    const int lane = tid & 31;
    const int wid  = tid >> 5;
    const int cta  = blockIdx.x;

    int layer, j0, nj;
    if (cta < 16) { layer = 0; nj = 32; j0 = cta * 32; }
    else {
        int r = cta - 16;
        layer = 1 + r / 44;
        int ci = r % 44;
        if (ci < 28) { nj = 12; j0 = ci * 12; }
        else         { nj = 11; j0 = 336 + (ci - 28) * 11; }
    }
    const int ngate = (layer == 0) ? 4 : 5;
    const int ncols = nj * ngate;
    const int K     = (layer == 0) ? 512 : 1024;
    const float* wbase = (layer == 0) ? w_hh : (ca_w + (size_t)(layer - 1) * G5 * 1024);
    const float* bbase = (layer == 0) ? nullptr : (ca_b + (size_t)(layer - 1) * G5);

    for (int s = 0; s < Tsz + 3; ++s) {
        const int t = s - layer;
        if (t >= 0 && t < Tsz) {
            // ---- stage hx = [h_low(t) ; h_prev(t-1)] (or just h_prev for layer 0) ----
            if (layer == 0) {
                if (t == 0) {
                    for (int e = tid; e < 512 * 32; e += NTHR) {
                        int b = e >> 9, k = e & 511;
                        hx[k * 33 + b] = 0.0f;
                    }
                } else {
                    const float* hp = g_h + ((size_t)(t - 1) * Bsz) * Hsz;
                    for (int e = tid; e < 512 * 32; e += NTHR) {
                        int b = e >> 9, k = e & 511;
                        hx[k * 33 + b] = __ldcg(hp + (size_t)b * Hsz + k);
                    }
                }
            } else {
                const float* hl = g_h + (((size_t)(layer - 1) * Tsz + t) * Bsz) * Hsz;
                const float* hp = (t > 0) ? g_h + (((size_t)layer * Tsz + (t - 1)) * Bsz) * Hsz : nullptr;
                for (int e = tid; e < 1024 * 32; e += NTHR) {
                    int b = e >> 10, k = e & 1023;
                    float v;
                    if (k < 512) v = __ldcg(hl + (size_t)b * Hsz + k);
                    else         v = hp ? __ldcg(hp + (size_t)b * Hsz + (k - 512)) : 0.0f;
                    hx[k * 33 + b] = v;
                }
            }
            __syncthreads();

            // ---- gate pre-activations: m[b, g*H+j] ----
            const float* xprow = g_xproj + ((size_t)t * Bsz + lane) * G4;
            for (int c = wid; c < ncols; c += (NTHR / 32)) {
                int g  = c / nj;
                int jj = c - g * nj;
                int row = g * Hsz + j0 + jj;
                const float* wr = wbase + (size_t)row * K;
                float init = (layer == 0) ? xprow[row] : bbase[row];
                float a0 = 0.0f, a1 = 0.0f;
                #pragma unroll 2
                for (int k = 0; k < K; k += 8) {
                    float4 wA = *reinterpret_cast<const float4*>(wr + k);
                    float4 wB = *reinterpret_cast<const float4*>(wr + k + 4);
                    const float* hk = hx + (size_t)k * 33 + lane;
                    a0 = fmaf(hk[0 * 33], wA.x, a0);
                    a1 = fmaf(hk[1 * 33], wA.y, a1);
                    a0 = fmaf(hk[2 * 33], wA.z, a0);
                    a1 = fmaf(hk[3 * 33], wA.w, a1);
                    a0 = fmaf(hk[4 * 33], wB.x, a0);
                    a1 = fmaf(hk[5 * 33], wB.y, a1);
                    a0 = fmaf(hk[6 * 33], wB.z, a0);
                    a1 = fmaf(hk[7 * 33], wB.w, a1);
                }
                ms[c * 32 + lane] = init + a0 + a1;
            }
            __syncthreads();

            // ---- activation + state update for this CTA's j-slice ----
            float* hout = g_h + (((size_t)layer * Tsz + t) * Bsz) * Hsz;
            float* cout = g_c + (((size_t)layer * Tsz + t) * Bsz) * Hsz;
            const float* cprev = (t > 0) ? g_c + (((size_t)layer * Tsz + (t - 1)) * Bsz) * Hsz : nullptr;
            if (layer == 0) {
                for (int it = tid; it < nj * 32; it += NTHR) {
                    int b = it / nj, jj = it - (it / nj) * nj;
                    int j = j0 + jj;
                    float i_ = ms[(0 * nj + jj) * 32 + b];
                    float f_ = ms[(1 * nj + jj) * 32 + b];
                    float gg = ms[(2 * nj + jj) * 32 + b];
                    float o_ = ms[(3 * nj + jj) * 32 + b];
                    float cp = cprev ? __ldcg(cprev + (size_t)b * Hsz + j) : 0.0f;
                    float cv = sigf(i_) * tanhf(gg) + sigf(f_) * cp;
                    float hv = sigf(o_) * tanhf(cv);
                    hout[(size_t)b * Hsz + j] = hv;
                    cout[(size_t)b * Hsz + j] = cv;
                }
            } else {
                const float* clow = g_c + (((size_t)(layer - 1) * Tsz + t) * Bsz) * Hsz;
                for (int it = tid; it < nj * 32; it += NTHR) {
                    int b = it / nj, jj = it - (it / nj) * nj;
                    int j = j0 + jj;
                    float i_ = ms[(0 * nj + jj) * 32 + b];
                    float fp = ms[(1 * nj + jj) * 32 + b];
                    float fl = ms[(2 * nj + jj) * 32 + b];
                    float u_ = ms[(3 * nj + jj) * 32 + b];
                    float o_ = ms[(4 * nj + jj) * 32 + b];
                    float cp = cprev ? __ldcg(cprev + (size_t)b * Hsz + j) : 0.0f;
                    float cl = __ldcg(clow + (size_t)b * Hsz + j);
                    float cv = cp * sigf(fp + 1.0f) + cl * sigf(fl + 1.0f) + tanhf(u_) * sigf(i_);
                    float hv = sigf(o_) * tanhf(cv);
                    hout[(size_t)b * Hsz + j] = hv;
                    cout[(size_t)b * Hsz + j] = cv;
                    if (layer == 3) {
                        out[(size_t)b * Tsz * Hsz + (size_t)t * Hsz + j] = hv;
                        out[BTHn + (size_t)b * Tsz * Hsz + (size_t)t * Hsz + j] = cv;
                        if (t == Tsz - 1) {
                            out[2 * BTHn + (size_t)b * Hsz + j] = hv;
                            out[2 * BTHn + (size_t)Bsz * Hsz + (size_t)b * Hsz + j] = cv;
                        }
                    }
                }
            }
        }

        // ---- grid barrier (monotonic counter, sense-free) ----
        __syncthreads();
        __threadfence();
        if (tid == 0) {
            atomicAdd(&g_bar, 1u);
            const unsigned tgt = (unsigned)NCTA * (unsigned)(s + 1);
            volatile unsigned* p = &g_bar;
            while (*p < tgt) { }
            __threadfence();
        }
        __syncthreads();
    }
}

extern "C" void kernel_launch(void* const* d_in, const int* in_sizes, int n_in,
                              void* d_out, int out_size)
{
    const float* x    = (const float*)d_in[0];
    const float* w_ih = (const float*)d_in[1];
    const float* w_hh = (const float*)d_in[2];
    const float* b_ih = (const float*)d_in[3];
    const float* b_hh = (const float*)d_in[4];
    const float* ca_w = (const float*)d_in[5];
    const float* ca_b = (const float*)d_in[6];
    float* out = (float*)d_out;

    (void)in_sizes; (void)n_in; (void)out_size;

    k_init<<<1, 32>>>();

    dim3 g(G4 / 64, (Tsz * Bsz) / 64);
    k_xproj<<<g, 256>>>(x, w_ih, b_ih, b_hh);

    const int smem_bytes = (1024 * 33 + 128 * 32) * (int)sizeof(float);  // 151552
    cudaFuncSetAttribute(k_wave, cudaFuncAttributeMaxDynamicSharedMemorySize, smem_bytes);
    k_wave<<<NCTA, NTHR, smem_bytes>>>(w_hh, ca_w, ca_b, out);
}

// round 2
// speedup vs baseline: 1.5342x; 1.5342x over previous
#include <cuda_runtime.h>
#include <cstdint>
#include <math.h>

#define Bsz 32
#define Tsz 512
#define DIsz 512
#define Hsz 512
#define G4 2048
#define G5 2560
#define NCTA 148
#define NTHR 512
#define BTHn ((size_t)32*512*512)

typedef unsigned long long ull;

// -------- static device scratch (alloc-free rule) --------
static __device__ float g_h[(size_t)4*512*32*512];       // h per layer,t,b,j  ([t][b][j])
static __device__ float g_c[(size_t)4*512*32*512];
static __device__ float g_xproj[(size_t)512*32*2048];    // x@w_ih.T + bias, (t,b,4H)
static __device__ unsigned g_bar;

__device__ __forceinline__ float sigf(float x) { return 1.0f / (1.0f + __expf(-x)); }

// packed fp32x2 FMA (sm_100+): d = a*b + c elementwise on 2 packed floats
__device__ __forceinline__ ull ffma2(ull a, ull b, ull c) {
    ull d;
    asm("fma.rn.f32x2 %0, %1, %2, %3;" : "=l"(d) : "l"(a), "l"(b), "l"(c));
    return d;
}
__device__ __forceinline__ float pairsum(ull a) {
    float lo, hi;
    asm("mov.b64 {%0, %1}, %2;" : "=f"(lo), "=f"(hi) : "l"(a));
    return lo + hi;
}

__global__ void k_init() { g_bar = 0u; }

// ---------------- xproj = x @ w_ih.T + (b_ih + b_hh) ----------------
__global__ void __launch_bounds__(256) k_xproj(
    const float* __restrict__ x, const float* __restrict__ w_ih,
    const float* __restrict__ b_ih, const float* __restrict__ b_hh)
{
    __shared__ float As[16][65];
    __shared__ float Bs[16][65];
    const int bm = blockIdx.y * 64;
    const int bn = blockIdx.x * 64;
    const int tid = threadIdx.x;
    const int tr = (tid >> 4) << 2;
    const int tc = (tid & 15) << 2;
    float acc[4][4] = {};
    for (int k0 = 0; k0 < DIsz; k0 += 16) {
        #pragma unroll
        for (int i0 = 0; i0 < 4; i0++) {
            int i  = i0 * 256 + tid;
            int mm = i >> 4, kk = i & 15;
            int m  = bm + mm;
            int tt = m >> 5, bb = m & 31;
            As[kk][mm] = x[((size_t)bb * Tsz + tt) * DIsz + (k0 + kk)];
            Bs[kk][mm] = w_ih[(size_t)(bn + mm) * DIsz + (k0 + kk)];
        }
        __syncthreads();
        #pragma unroll
        for (int kk = 0; kk < 16; kk++) {
            float a0 = As[kk][tr+0], a1 = As[kk][tr+1], a2 = As[kk][tr+2], a3 = As[kk][tr+3];
            float b0 = Bs[kk][tc+0], b1 = Bs[kk][tc+1], b2 = Bs[kk][tc+2], b3 = Bs[kk][tc+3];
            acc[0][0] = fmaf(a0,b0,acc[0][0]); acc[0][1] = fmaf(a0,b1,acc[0][1]);
            acc[0][2] = fmaf(a0,b2,acc[0][2]); acc[0][3] = fmaf(a0,b3,acc[0][3]);
            acc[1][0] = fmaf(a1,b0,acc[1][0]); acc[1][1] = fmaf(a1,b1,acc[1][1]);
            acc[1][2] = fmaf(a1,b2,acc[1][2]); acc[1][3] = fmaf(a1,b3,acc[1][3]);
            acc[2][0] = fmaf(a2,b0,acc[2][0]); acc[2][1] = fmaf(a2,b1,acc[2][1]);
            acc[2][2] = fmaf(a2,b2,acc[2][2]); acc[2][3] = fmaf(a2,b3,acc[2][3]);
            acc[3][0] = fmaf(a3,b0,acc[3][0]); acc[3][1] = fmaf(a3,b1,acc[3][1]);
            acc[3][2] = fmaf(a3,b2,acc[3][2]); acc[3][3] = fmaf(a3,b3,acc[3][3]);
        }
        __syncthreads();
    }
    #pragma unroll
    for (int i = 0; i < 4; i++) {
        #pragma unroll
        for (int j = 0; j < 4; j++) {
            int n = bn + tc + j;
            g_xproj[(size_t)(bm + tr + i) * G4 + n] = acc[i][j] + b_ih[n] + b_hh[n];
        }
    }
}

// ---------------- persistent wavefront LSTM ----------------
// hx staged as packed fp32 PAIRS: pair k2 at [k2*66 + 2*b (+0/1)]  (bank-conflict-free)
// Each warp computes 4 gate rows at once, reusing each LDS.64 of h 4x.
__global__ void __launch_bounds__(NTHR, 1) k_wave(
    const float* __restrict__ w_hh, const float* __restrict__ ca_w,
    const float* __restrict__ ca_b, float* __restrict__ out)
{
    extern __shared__ float sm[];
    float* hx = sm;                 // 512 pairs * 66 floats = 33792 floats
    float* ms = sm + 512 * 66;      // [c*32 + b], c < 128

    const int tid  = threadIdx.x;
    const int lane = tid & 31;
    const int wid  = tid >> 5;
    const int cta  = blockIdx.x;

    int layer, j0, nj;
    if (cta < 16) { layer = 0; nj = 32; j0 = cta * 32; }
    else {
        int r = cta - 16;
        layer = 1 + r / 44;
        int ci = r % 44;
        if (ci < 28) { nj = 12; j0 = ci * 12; }
        else         { nj = 11; j0 = 336 + (ci - 28) * 11; }
    }
    const int ngate = (layer == 0) ? 4 : 5;
    const int ncols = nj * ngate;
    const int K     = (layer == 0) ? 512 : 1024;
    const int NP    = K >> 1;  // pairs
    const float* wbase = (layer == 0) ? w_hh : (ca_w + (size_t)(layer - 1) * G5 * 1024);
    const float* bbase = (layer == 0) ? nullptr : (ca_b + (size_t)(layer - 1) * G5);

    for (int s = 0; s < Tsz + 3; ++s) {
        const int t = s - layer;
        if (t >= 0 && t < Tsz) {
            // ---- stage hx pairs = [h_low(t) ; h_prev(t-1)] ----
            if (layer == 0) {
                const float* hp = (t > 0) ? g_h + ((size_t)(t - 1) * Bsz) * Hsz : nullptr;
                for (int e = tid; e < 512 * 32; e += NTHR) {
                    int b = e >> 9, k = e & 511;
                    float v = hp ? __ldcg(hp + (size_t)b * Hsz + k) : 0.0f;
                    hx[(k >> 1) * 66 + 2 * b + (k & 1)] = v;
                }
            } else {
                const float* hl = g_h + (((size_t)(layer - 1) * Tsz + t) * Bsz) * Hsz;
                const float* hp = (t > 0) ? g_h + (((size_t)layer * Tsz + (t - 1)) * Bsz) * Hsz : nullptr;
                for (int e = tid; e < 1024 * 32; e += NTHR) {
                    int b = e >> 10, k = e & 1023;
                    float v;
                    if (k < 512) v = __ldcg(hl + (size_t)b * Hsz + k);
                    else         v = hp ? __ldcg(hp + (size_t)b * Hsz + (k - 512)) : 0.0f;
                    hx[(k >> 1) * 66 + 2 * b + (k & 1)] = v;
                }
            }
            __syncthreads();

            // ---- gate pre-activations, 4 rows per warp per pass ----
            const float* xprow = g_xproj + ((size_t)t * Bsz + lane) * G4;
            for (int cg = wid * 4; cg < ncols; cg += (NTHR / 32) * 4) {
                int c0 = cg, c1 = min(cg + 1, ncols - 1),
                    c2 = min(cg + 2, ncols - 1), c3 = min(cg + 3, ncols - 1);
                int r0 = (c0 / nj) * Hsz + j0 + (c0 % nj);
                int r1 = (c1 / nj) * Hsz + j0 + (c1 % nj);
                int r2 = (c2 / nj) * Hsz + j0 + (c2 % nj);
                int r3 = (c3 / nj) * Hsz + j0 + (c3 % nj);
                const ull* w0 = (const ull*)(wbase + (size_t)r0 * K);
                const ull* w1 = (const ull*)(wbase + (size_t)r1 * K);
                const ull* w2 = (const ull*)(wbase + (size_t)r2 * K);
                const ull* w3 = (const ull*)(wbase + (size_t)r3 * K);
                ull a0A = 0, a0B = 0, a1A = 0, a1B = 0;
                ull a2A = 0, a2B = 0, a3A = 0, a3B = 0;
                const float* hb = hx + 2 * lane;
                #pragma unroll 2
                for (int p = 0; p < NP; p += 4) {
                    ull h0 = *(const ull*)(hb + (p + 0) * 66);
                    ull h1 = *(const ull*)(hb + (p + 1) * 66);
                    ull h2 = *(const ull*)(hb + (p + 2) * 66);
                    ull h3 = *(const ull*)(hb + (p + 3) * 66);
                    ulonglong2 wA0 = *(const ulonglong2*)(w0 + p);
                    ulonglong2 wB0 = *(const ulonglong2*)(w0 + p + 2);
                    ulonglong2 wA1 = *(const ulonglong2*)(w1 + p);
                    ulonglong2 wB1 = *(const ulonglong2*)(w1 + p + 2);
                    ulonglong2 wA2 = *(const ulonglong2*)(w2 + p);
                    ulonglong2 wB2 = *(const ulonglong2*)(w2 + p + 2);
                    ulonglong2 wA3 = *(const ulonglong2*)(w3 + p);
                    ulonglong2 wB3 = *(const ulonglong2*)(w3 + p + 2);
                    a0A = ffma2(h0, wA0.x, a0A); a0B = ffma2(h1, wA0.y, a0B);
                    a1A = ffma2(h0, wA1.x, a1A); a1B = ffma2(h1, wA1.y, a1B);
                    a2A = ffma2(h0, wA2.x, a2A); a2B = ffma2(h1, wA2.y, a2B);
                    a3A = ffma2(h0, wA3.x, a3A); a3B = ffma2(h1, wA3.y, a3B);
                    a0A = ffma2(h2, wB0.x, a0A); a0B = ffma2(h3, wB0.y, a0B);
                    a1A = ffma2(h2, wB1.x, a1A); a1B = ffma2(h3, wB1.y, a1B);
                    a2A = ffma2(h2, wB2.x, a2A); a2B = ffma2(h3, wB2.y, a2B);
                    a3A = ffma2(h2, wB3.x, a3A); a3B = ffma2(h3, wB3.y, a3B);
                }
                float i0 = (layer == 0) ? xprow[r0] : bbase[r0];
                float i1 = (layer == 0) ? xprow[r1] : bbase[r1];
                float i2 = (layer == 0) ? xprow[r2] : bbase[r2];
                float i3 = (layer == 0) ? xprow[r3] : bbase[r3];
                ms[c0 * 32 + lane] = i0 + pairsum(a0A) + pairsum(a0B);
                if (cg + 1 < ncols) ms[c1 * 32 + lane] = i1 + pairsum(a1A) + pairsum(a1B);
                if (cg + 2 < ncols) ms[c2 * 32 + lane] = i2 + pairsum(a2A) + pairsum(a2B);
                if (cg + 3 < ncols) ms[c3 * 32 + lane] = i3 + pairsum(a3A) + pairsum(a3B);
            }
            __syncthreads();

            // ---- activation + state update ----
            float* hout = g_h + (((size_t)layer * Tsz + t) * Bsz) * Hsz;
            float* cout = g_c + (((size_t)layer * Tsz + t) * Bsz) * Hsz;
            const float* cprev = (t > 0) ? g_c + (((size_t)layer * Tsz + (t - 1)) * Bsz) * Hsz : nullptr;
            if (layer == 0) {
                for (int it = tid; it < nj * 32; it += NTHR) {
                    int b = it / nj, jj = it - (it / nj) * nj;
                    int j = j0 + jj;
                    float i_ = ms[(0 * nj + jj) * 32 + b];
                    float f_ = ms[(1 * nj + jj) * 32 + b];
                    float gg = ms[(2 * nj + jj) * 32 + b];
                    float o_ = ms[(3 * nj + jj) * 32 + b];
                    float cp = cprev ? __ldcg(cprev + (size_t)b * Hsz + j) : 0.0f;
                    float cv = sigf(i_) * tanhf(gg) + sigf(f_) * cp;
                    float hv = sigf(o_) * tanhf(cv);
                    hout[(size_t)b * Hsz + j] = hv;
                    cout[(size_t)b * Hsz + j] = cv;
                }
            } else {
                const float* clow = g_c + (((size_t)(layer - 1) * Tsz + t) * Bsz) * Hsz;
                for (int it = tid; it < nj * 32; it += NTHR) {
                    int b = it / nj, jj = it - (it / nj) * nj;
                    int j = j0 + jj;
                    float i_ = ms[(0 * nj + jj) * 32 + b];
                    float fp = ms[(1 * nj + jj) * 32 + b];
                    float fl = ms[(2 * nj + jj) * 32 + b];
                    float u_ = ms[(3 * nj + jj) * 32 + b];
                    float o_ = ms[(4 * nj + jj) * 32 + b];
                    float cp = cprev ? __ldcg(cprev + (size_t)b * Hsz + j) : 0.0f;
                    float cl = __ldcg(clow + (size_t)b * Hsz + j);
                    float cv = cp * sigf(fp + 1.0f) + cl * sigf(fl + 1.0f) + tanhf(u_) * sigf(i_);
                    float hv = sigf(o_) * tanhf(cv);
                    hout[(size_t)b * Hsz + j] = hv;
                    cout[(size_t)b * Hsz + j] = cv;
                    if (layer == 3) {
                        out[(size_t)b * Tsz * Hsz + (size_t)t * Hsz + j] = hv;
                        out[BTHn + (size_t)b * Tsz * Hsz + (size_t)t * Hsz + j] = cv;
                        if (t == Tsz - 1) {
                            out[2 * BTHn + (size_t)b * Hsz + j] = hv;
                            out[2 * BTHn + (size_t)Bsz * Hsz + (size_t)b * Hsz + j] = cv;
                        }
                    }
                }
            }
        }

        // ---- grid barrier (monotonic counter) ----
        __syncthreads();
        __threadfence();
        if (tid == 0) {
            atomicAdd(&g_bar, 1u);
            const unsigned tgt = (unsigned)NCTA * (unsigned)(s + 1);
            volatile unsigned* p = &g_bar;
            while (*p < tgt) { }
            __threadfence();
        }
        __syncthreads();
    }
}

extern "C" void kernel_launch(void* const* d_in, const int* in_sizes, int n_in,
                              void* d_out, int out_size)
{
    const float* x    = (const float*)d_in[0];
    const float* w_ih = (const float*)d_in[1];
    const float* w_hh = (const float*)d_in[2];
    const float* b_ih = (const float*)d_in[3];
    const float* b_hh = (const float*)d_in[4];
    const float* ca_w = (const float*)d_in[5];
    const float* ca_b = (const float*)d_in[6];
    float* out = (float*)d_out;

    (void)in_sizes; (void)n_in; (void)out_size;

    k_init<<<1, 32>>>();

    dim3 g(G4 / 64, (Tsz * Bsz) / 64);
    k_xproj<<<g, 256>>>(x, w_ih, b_ih, b_hh);

    const int smem_bytes = (512 * 66 + 128 * 32) * (int)sizeof(float);  // 151552
    cudaFuncSetAttribute(k_wave, cudaFuncAttributeMaxDynamicSharedMemorySize, smem_bytes);
    k_wave<<<NCTA, NTHR, smem_bytes>>>(w_hh, ca_w, ca_b, out);
}

// round 3
// speedup vs baseline: 1.5677x; 1.0218x over previous
#include <cuda_runtime.h>
#include <cstdint>
#include <math.h>

#define Bsz 32
#define Tsz 512
#define DIsz 512
#define Hsz 512
#define G4 2048
#define G5 2560
#define NCTA 148
#define NTHR 512
#define BTHn ((size_t)32*512*512)

typedef unsigned long long ull;

// -------- static device scratch (alloc-free rule) --------
static __device__ float g_h[(size_t)4*512*32*512];       // h per layer,t,b,j  ([t][b][j])
static __device__ float g_c[(size_t)4*512*32*512];
static __device__ float g_xproj[(size_t)512*32*2048];    // x@w_ih.T + bias, (t,b,4H)
static __device__ unsigned g_bar;

__device__ __forceinline__ float sigf(float x) { return 1.0f / (1.0f + __expf(-x)); }

// packed fp32x2 FMA (sm_100+): d = a*b + c elementwise on 2 packed floats
__device__ __forceinline__ ull ffma2(ull a, ull b, ull c) {
    ull d;
    asm("fma.rn.f32x2 %0, %1, %2, %3;" : "=l"(d) : "l"(a), "l"(b), "l"(c));
    return d;
}
__device__ __forceinline__ float pairsum(ull a) {
    float lo, hi;
    asm("mov.b64 {%0, %1}, %2;" : "=f"(lo), "=f"(hi) : "l"(a));
    return lo + hi;
}

__global__ void k_init() { g_bar = 0u; }

// ---------------- xproj = x @ w_ih.T + (b_ih + b_hh) ----------------
__global__ void __launch_bounds__(256) k_xproj(
    const float* __restrict__ x, const float* __restrict__ w_ih,
    const float* __restrict__ b_ih, const float* __restrict__ b_hh)
{
    __shared__ float As[16][65];
    __shared__ float Bs[16][65];
    const int bm = blockIdx.y * 64;
    const int bn = blockIdx.x * 64;
    const int tid = threadIdx.x;
    const int tr = (tid >> 4) << 2;
    const int tc = (tid & 15) << 2;
    float acc[4][4] = {};
    for (int k0 = 0; k0 < DIsz; k0 += 16) {
        #pragma unroll
        for (int i0 = 0; i0 < 4; i0++) {
            int i  = i0 * 256 + tid;
            int mm = i >> 4, kk = i & 15;
            int m  = bm + mm;
            int tt = m >> 5, bb = m & 31;
            As[kk][mm] = x[((size_t)bb * Tsz + tt) * DIsz + (k0 + kk)];
            Bs[kk][mm] = w_ih[(size_t)(bn + mm) * DIsz + (k0 + kk)];
        }
        __syncthreads();
        #pragma unroll
        for (int kk = 0; kk < 16; kk++) {
            float a0 = As[kk][tr+0], a1 = As[kk][tr+1], a2 = As[kk][tr+2], a3 = As[kk][tr+3];
            float b0 = Bs[kk][tc+0], b1 = Bs[kk][tc+1], b2 = Bs[kk][tc+2], b3 = Bs[kk][tc+3];
            acc[0][0] = fmaf(a0,b0,acc[0][0]); acc[0][1] = fmaf(a0,b1,acc[0][1]);
            acc[0][2] = fmaf(a0,b2,acc[0][2]); acc[0][3] = fmaf(a0,b3,acc[0][3]);
            acc[1][0] = fmaf(a1,b0,acc[1][0]); acc[1][1] = fmaf(a1,b1,acc[1][1]);
            acc[1][2] = fmaf(a1,b2,acc[1][2]); acc[1][3] = fmaf(a1,b3,acc[1][3]);
            acc[2][0] = fmaf(a2,b0,acc[2][0]); acc[2][1] = fmaf(a2,b1,acc[2][1]);
            acc[2][2] = fmaf(a2,b2,acc[2][2]); acc[2][3] = fmaf(a2,b3,acc[2][3]);
            acc[3][0] = fmaf(a3,b0,acc[3][0]); acc[3][1] = fmaf(a3,b1,acc[3][1]);
            acc[3][2] = fmaf(a3,b2,acc[3][2]); acc[3][3] = fmaf(a3,b3,acc[3][3]);
        }
        __syncthreads();
    }
    #pragma unroll
    for (int i = 0; i < 4; i++) {
        #pragma unroll
        for (int j = 0; j < 4; j++) {
            int n = bn + tc + j;
            g_xproj[(size_t)(bm + tr + i) * G4 + n] = acc[i][j] + b_ih[n] + b_hh[n];
        }
    }
}

// ---------------- persistent wavefront LSTM ----------------
// hx staged as packed fp32 PAIRS: pair k2 at [k2*66 + 2*b (+0/1)]  (bank-conflict-free)
// Each warp computes 4 gate rows at once, reusing each LDS.64 of h 4x.
__global__ void __launch_bounds__(NTHR, 1) k_wave(
    const float* __restrict__ w_hh, const float* __restrict__ ca_w,
    const float* __restrict__ ca_b, float* __restrict__ out)
{
    extern __shared__ float sm[];
    float* hx = sm;                 // 512 pairs * 66 floats = 33792 floats
    float* ms = sm + 512 * 66;      // [c*32 + b], c < 128

    const int tid  = threadIdx.x;
    const int lane = tid & 31;
    const int wid  = tid >> 5;
    const int cta  = blockIdx.x;

    int layer, j0, nj;
    if (cta < 16) { layer = 0; nj = 32; j0 = cta * 32; }
    else {
        int r = cta - 16;
        layer = 1 + r / 44;
        int ci = r % 44;
        if (ci < 28) { nj = 12; j0 = ci * 12; }
        else         { nj = 11; j0 = 336 + (ci - 28) * 11; }
    }
    const int ngate = (layer == 0) ? 4 : 5;
    const int ncols = nj * ngate;
    const int K     = (layer == 0) ? 512 : 1024;
    const int NP    = K >> 1;  // pairs
    const float* wbase = (layer == 0) ? w_hh : (ca_w + (size_t)(layer - 1) * G5 * 1024);
    const float* bbase = (layer == 0) ? nullptr : (ca_b + (size_t)(layer - 1) * G5);

    for (int s = 0; s < Tsz + 3; ++s) {
        const int t = s - layer;
        if (t >= 0 && t < Tsz) {
            // ---- stage hx pairs = [h_low(t) ; h_prev(t-1)] ----
            if (layer == 0) {
                const float* hp = (t > 0) ? g_h + ((size_t)(t - 1) * Bsz) * Hsz : nullptr;
                for (int e = tid; e < 512 * 32; e += NTHR) {
                    int b = e >> 9, k = e & 511;
                    float v = hp ? __ldcg(hp + (size_t)b * Hsz + k) : 0.0f;
                    hx[(k >> 1) * 66 + 2 * b + (k & 1)] = v;
                }
            } else {
                const float* hl = g_h + (((size_t)(layer - 1) * Tsz + t) * Bsz) * Hsz;
                const float* hp = (t > 0) ? g_h + (((size_t)layer * Tsz + (t - 1)) * Bsz) * Hsz : nullptr;
                for (int e = tid; e < 1024 * 32; e += NTHR) {
                    int b = e >> 10, k = e & 1023;
                    float v;
                    if (k < 512) v = __ldcg(hl + (size_t)b * Hsz + k);
                    else         v = hp ? __ldcg(hp + (size_t)b * Hsz + (k - 512)) : 0.0f;
                    hx[(k >> 1) * 66 + 2 * b + (k & 1)] = v;
                }
            }
            __syncthreads();

            // ---- gate pre-activations, 4 rows per warp per pass ----
            const float* xprow = g_xproj + ((size_t)t * Bsz + lane) * G4;
            for (int cg = wid * 4; cg < ncols; cg += (NTHR / 32) * 4) {
                int c0 = cg, c1 = min(cg + 1, ncols - 1),
                    c2 = min(cg + 2, ncols - 1), c3 = min(cg + 3, ncols - 1);
                int r0 = (c0 / nj) * Hsz + j0 + (c0 % nj);
                int r1 = (c1 / nj) * Hsz + j0 + (c1 % nj);
                int r2 = (c2 / nj) * Hsz + j0 + (c2 % nj);
                int r3 = (c3 / nj) * Hsz + j0 + (c3 % nj);
                const ull* w0 = (const ull*)(wbase + (size_t)r0 * K);
                const ull* w1 = (const ull*)(wbase + (size_t)r1 * K);
                const ull* w2 = (const ull*)(wbase + (size_t)r2 * K);
                const ull* w3 = (const ull*)(wbase + (size_t)r3 * K);
                ull a0A = 0, a0B = 0, a1A = 0, a1B = 0;
                ull a2A = 0, a2B = 0, a3A = 0, a3B = 0;
                const float* hb = hx + 2 * lane;
                #pragma unroll 2
                for (int p = 0; p < NP; p += 4) {
                    ull h0 = *(const ull*)(hb + (p + 0) * 66);
                    ull h1 = *(const ull*)(hb + (p + 1) * 66);
                    ull h2 = *(const ull*)(hb + (p + 2) * 66);
                    ull h3 = *(const ull*)(hb + (p + 3) * 66);
                    ulonglong2 wA0 = *(const ulonglong2*)(w0 + p);
                    ulonglong2 wB0 = *(const ulonglong2*)(w0 + p + 2);
                    ulonglong2 wA1 = *(const ulonglong2*)(w1 + p);
                    ulonglong2 wB1 = *(const ulonglong2*)(w1 + p + 2);
                    ulonglong2 wA2 = *(const ulonglong2*)(w2 + p);
                    ulonglong2 wB2 = *(const ulonglong2*)(w2 + p + 2);
                    ulonglong2 wA3 = *(const ulonglong2*)(w3 + p);
                    ulonglong2 wB3 = *(const ulonglong2*)(w3 + p + 2);
                    a0A = ffma2(h0, wA0.x, a0A); a0B = ffma2(h1, wA0.y, a0B);
                    a1A = ffma2(h0, wA1.x, a1A); a1B = ffma2(h1, wA1.y, a1B);
                    a2A = ffma2(h0, wA2.x, a2A); a2B = ffma2(h1, wA2.y, a2B);
                    a3A = ffma2(h0, wA3.x, a3A); a3B = ffma2(h1, wA3.y, a3B);
                    a0A = ffma2(h2, wB0.x, a0A); a0B = ffma2(h3, wB0.y, a0B);
                    a1A = ffma2(h2, wB1.x, a1A); a1B = ffma2(h3, wB1.y, a1B);
                    a2A = ffma2(h2, wB2.x, a2A); a2B = ffma2(h3, wB2.y, a2B);
                    a3A = ffma2(h2, wB3.x, a3A); a3B = ffma2(h3, wB3.y, a3B);
                }
                float i0 = (layer == 0) ? xprow[r0] : bbase[r0];
                float i1 = (layer == 0) ? xprow[r1] : bbase[r1];
                float i2 = (layer == 0) ? xprow[r2] : bbase[r2];
                float i3 = (layer == 0) ? xprow[r3] : bbase[r3];
                ms[c0 * 32 + lane] = i0 + pairsum(a0A) + pairsum(a0B);
                if (cg + 1 < ncols) ms[c1 * 32 + lane] = i1 + pairsum(a1A) + pairsum(a1B);
                if (cg + 2 < ncols) ms[c2 * 32 + lane] = i2 + pairsum(a2A) + pairsum(a2B);
                if (cg + 3 < ncols) ms[c3 * 32 + lane] = i3 + pairsum(a3A) + pairsum(a3B);
            }
            __syncthreads();

            // ---- activation + state update ----
            float* hout = g_h + (((size_t)layer * Tsz + t) * Bsz) * Hsz;
            float* cout = g_c + (((size_t)layer * Tsz + t) * Bsz) * Hsz;
            const float* cprev = (t > 0) ? g_c + (((size_t)layer * Tsz + (t - 1)) * Bsz) * Hsz : nullptr;
            if (layer == 0) {
                for (int it = tid; it < nj * 32; it += NTHR) {
                    int b = it / nj, jj = it - (it / nj) * nj;
                    int j = j0 + jj;
                    float i_ = ms[(0 * nj + jj) * 32 + b];
                    float f_ = ms[(1 * nj + jj) * 32 + b];
                    float gg = ms[(2 * nj + jj) * 32 + b];
                    float o_ = ms[(3 * nj + jj) * 32 + b];
                    float cp = cprev ? __ldcg(cprev + (size_t)b * Hsz + j) : 0.0f;
                    float cv = sigf(i_) * tanhf(gg) + sigf(f_) * cp;
                    float hv = sigf(o_) * tanhf(cv);
                    hout[(size_t)b * Hsz + j] = hv;
                    cout[(size_t)b * Hsz + j] = cv;
                }
            } else {
                const float* clow = g_c + (((size_t)(layer - 1) * Tsz + t) * Bsz) * Hsz;
                for (int it = tid; it < nj * 32; it += NTHR) {
                    int b = it / nj, jj = it - (it / nj) * nj;
                    int j = j0 + jj;
                    float i_ = ms[(0 * nj + jj) * 32 + b];
                    float fp = ms[(1 * nj + jj) * 32 + b];
                    float fl = ms[(2 * nj + jj) * 32 + b];
                    float u_ = ms[(3 * nj + jj) * 32 + b];
                    float o_ = ms[(4 * nj + jj) * 32 + b];
                    float cp = cprev ? __ldcg(cprev + (size_t)b * Hsz + j) : 0.0f;
                    float cl = __ldcg(clow + (size_t)b * Hsz + j);
                    float cv = cp * sigf(fp + 1.0f) + cl * sigf(fl + 1.0f) + tanhf(u_) * sigf(i_);
                    float hv = sigf(o_) * tanhf(cv);
                    hout[(size_t)b * Hsz + j] = hv;
                    cout[(size_t)b * Hsz + j] = cv;
                    if (layer == 3) {
                        out[(size_t)b * Tsz * Hsz + (size_t)t * Hsz + j] = hv;
                        out[BTHn + (size_t)b * Tsz * Hsz + (size_t)t * Hsz + j] = cv;
                        if (t == Tsz - 1) {
                            out[2 * BTHn + (size_t)b * Hsz + j] = hv;
                            out[2 * BTHn + (size_t)Bsz * Hsz + (size_t)b * Hsz + j] = cv;
                        }
                    }
                }
            }
        }

        // ---- grid barrier (monotonic counter) ----
        __syncthreads();
        __threadfence();
        if (tid == 0) {
            atomicAdd(&g_bar, 1u);
            const unsigned tgt = (unsigned)NCTA * (unsigned)(s + 1);
            volatile unsigned* p = &g_bar;
            while (*p < tgt) { }
            __threadfence();
        }
        __syncthreads();
    }
}

extern "C" void kernel_launch(void* const* d_in, const int* in_sizes, int n_in,
                              void* d_out, int out_size)
{
    const float* x    = (const float*)d_in[0];
    const float* w_ih = (const float*)d_in[1];
    const float* w_hh = (const float*)d_in[2];
    const float* b_ih = (const float*)d_in[3];
    const float* b_hh = (const float*)d_in[4];
    const float* ca_w = (const float*)d_in[5];
    const float* ca_b = (const float*)d_in[6];
    float* out = (float*)d_out;

    (void)in_sizes; (void)n_in; (void)out_size;

    k_init<<<1, 32>>>();

    dim3 g(G4 / 64, (Tsz * Bsz) / 64);
    k_xproj<<<g, 256>>>(x, w_ih, b_ih, b_hh);

    const int smem_bytes = (512 * 66 + 128 * 32) * (int)sizeof(float);  // 151552
    cudaFuncSetAttribute(k_wave, cudaFuncAttributeMaxDynamicSharedMemorySize, smem_bytes);
    k_wave<<<NCTA, NTHR, smem_bytes>>>(w_hh, ca_w, ca_b, out);
}

// round 4
// speedup vs baseline: 1.5689x; 1.0008x over previous
#include <cuda_runtime.h>
#include <cstdint>
#include <math.h>

#define Bsz 32
#define Tsz 512
#define DIsz 512
#define Hsz 512
#define G4 2048
#define G5 2560
#define NCTA 148
#define NTHR 512
#define BTHn ((size_t)32*512*512)

typedef unsigned long long ull;

// -------- static device scratch (alloc-free rule) --------
static __device__ float g_h[(size_t)4*512*32*512];       // h per layer,t,b,j  ([t][b][j])
static __device__ float g_c[(size_t)4*512*32*512];
static __device__ float g_xproj[(size_t)512*32*2048];    // x@w_ih.T + bias, (t,b,4H)
static __device__ unsigned g_bar;

__device__ __forceinline__ float sigf(float x) { return 1.0f / (1.0f + __expf(-x)); }

// packed fp32x2 FMA (sm_100+): d = a*b + c elementwise on 2 packed floats
__device__ __forceinline__ ull ffma2(ull a, ull b, ull c) {
    ull d;
    asm("fma.rn.f32x2 %0, %1, %2, %3;" : "=l"(d) : "l"(a), "l"(b), "l"(c));
    return d;
}
__device__ __forceinline__ float pairsum(ull a) {
    float lo, hi;
    asm("mov.b64 {%0, %1}, %2;" : "=f"(lo), "=f"(hi) : "l"(a));
    return lo + hi;
}

__global__ void k_init() { g_bar = 0u; }

// ---------------- xproj = x @ w_ih.T + (b_ih + b_hh) ----------------
__global__ void __launch_bounds__(256) k_xproj(
    const float* __restrict__ x, const float* __restrict__ w_ih,
    const float* __restrict__ b_ih, const float* __restrict__ b_hh)
{
    __shared__ float As[16][65];
    __shared__ float Bs[16][65];
    const int bm = blockIdx.y * 64;
    const int bn = blockIdx.x * 64;
    const int tid = threadIdx.x;
    const int tr = (tid >> 4) << 2;
    const int tc = (tid & 15) << 2;
    float acc[4][4] = {};
    for (int k0 = 0; k0 < DIsz; k0 += 16) {
        #pragma unroll
        for (int i0 = 0; i0 < 4; i0++) {
            int i  = i0 * 256 + tid;
            int mm = i >> 4, kk = i & 15;
            int m  = bm + mm;
            int tt = m >> 5, bb = m & 31;
            As[kk][mm] = x[((size_t)bb * Tsz + tt) * DIsz + (k0 + kk)];
            Bs[kk][mm] = w_ih[(size_t)(bn + mm) * DIsz + (k0 + kk)];
        }
        __syncthreads();
        #pragma unroll
        for (int kk = 0; kk < 16; kk++) {
            float a0 = As[kk][tr+0], a1 = As[kk][tr+1], a2 = As[kk][tr+2], a3 = As[kk][tr+3];
            float b0 = Bs[kk][tc+0], b1 = Bs[kk][tc+1], b2 = Bs[kk][tc+2], b3 = Bs[kk][tc+3];
            acc[0][0] = fmaf(a0,b0,acc[0][0]); acc[0][1] = fmaf(a0,b1,acc[0][1]);
            acc[0][2] = fmaf(a0,b2,acc[0][2]); acc[0][3] = fmaf(a0,b3,acc[0][3]);
            acc[1][0] = fmaf(a1,b0,acc[1][0]); acc[1][1] = fmaf(a1,b1,acc[1][1]);
            acc[1][2] = fmaf(a1,b2,acc[1][2]); acc[1][3] = fmaf(a1,b3,acc[1][3]);
            acc[2][0] = fmaf(a2,b0,acc[2][0]); acc[2][1] = fmaf(a2,b1,acc[2][1]);
            acc[2][2] = fmaf(a2,b2,acc[2][2]); acc[2][3] = fmaf(a2,b3,acc[2][3]);
            acc[3][0] = fmaf(a3,b0,acc[3][0]); acc[3][1] = fmaf(a3,b1,acc[3][1]);
            acc[3][2] = fmaf(a3,b2,acc[3][2]); acc[3][3] = fmaf(a3,b3,acc[3][3]);
        }
        __syncthreads();
    }
    #pragma unroll
    for (int i = 0; i < 4; i++) {
        #pragma unroll
        for (int j = 0; j < 4; j++) {
            int n = bn + tc + j;
            g_xproj[(size_t)(bm + tr + i) * G4 + n] = acc[i][j] + b_ih[n] + b_hh[n];
        }
    }
}

// ---------------- persistent wavefront LSTM ----------------
// hx staged as packed fp32 PAIRS: pair k2 at [k2*66 + 2*b (+0/1)]  (bank-conflict-free)
// Each warp computes 4 gate rows at once, reusing each LDS.64 of h 4x.
__global__ void __launch_bounds__(NTHR, 1) k_wave(
    const float* __restrict__ w_hh, const float* __restrict__ ca_w,
    const float* __restrict__ ca_b, float* __restrict__ out)
{
    extern __shared__ float sm[];
    float* hx = sm;                 // 512 pairs * 66 floats = 33792 floats
    float* ms = sm + 512 * 66;      // [c*32 + b], c < 128

    const int tid  = threadIdx.x;
    const int lane = tid & 31;
    const int wid  = tid >> 5;
    const int cta  = blockIdx.x;

    int layer, j0, nj;
    if (cta < 16) { layer = 0; nj = 32; j0 = cta * 32; }
    else {
        int r = cta - 16;
        layer = 1 + r / 44;
        int ci = r % 44;
        if (ci < 28) { nj = 12; j0 = ci * 12; }
        else         { nj = 11; j0 = 336 + (ci - 28) * 11; }
    }
    const int ngate = (layer == 0) ? 4 : 5;
    const int ncols = nj * ngate;
    const int K     = (layer == 0) ? 512 : 1024;
    const int NP    = K >> 1;  // pairs
    const float* wbase = (layer == 0) ? w_hh : (ca_w + (size_t)(layer - 1) * G5 * 1024);
    const float* bbase = (layer == 0) ? nullptr : (ca_b + (size_t)(layer - 1) * G5);

    for (int s = 0; s < Tsz + 3; ++s) {
        const int t = s - layer;
        if (t >= 0 && t < Tsz) {
            // ---- stage hx pairs = [h_low(t) ; h_prev(t-1)] ----
            if (layer == 0) {
                const float* hp = (t > 0) ? g_h + ((size_t)(t - 1) * Bsz) * Hsz : nullptr;
                for (int e = tid; e < 512 * 32; e += NTHR) {
                    int b = e >> 9, k = e & 511;
                    float v = hp ? __ldcg(hp + (size_t)b * Hsz + k) : 0.0f;
                    hx[(k >> 1) * 66 + 2 * b + (k & 1)] = v;
                }
            } else {
                const float* hl = g_h + (((size_t)(layer - 1) * Tsz + t) * Bsz) * Hsz;
                const float* hp = (t > 0) ? g_h + (((size_t)layer * Tsz + (t - 1)) * Bsz) * Hsz : nullptr;
                for (int e = tid; e < 1024 * 32; e += NTHR) {
                    int b = e >> 10, k = e & 1023;
                    float v;
                    if (k < 512) v = __ldcg(hl + (size_t)b * Hsz + k);
                    else         v = hp ? __ldcg(hp + (size_t)b * Hsz + (k - 512)) : 0.0f;
                    hx[(k >> 1) * 66 + 2 * b + (k & 1)] = v;
                }
            }
            __syncthreads();

            // ---- gate pre-activations, 4 rows per warp per pass ----
            const float* xprow = g_xproj + ((size_t)t * Bsz + lane) * G4;
            for (int cg = wid * 4; cg < ncols; cg += (NTHR / 32) * 4) {
                int c0 = cg, c1 = min(cg + 1, ncols - 1),
                    c2 = min(cg + 2, ncols - 1), c3 = min(cg + 3, ncols - 1);
                int r0 = (c0 / nj) * Hsz + j0 + (c0 % nj);
                int r1 = (c1 / nj) * Hsz + j0 + (c1 % nj);
                int r2 = (c2 / nj) * Hsz + j0 + (c2 % nj);
                int r3 = (c3 / nj) * Hsz + j0 + (c3 % nj);
                const ull* w0 = (const ull*)(wbase + (size_t)r0 * K);
                const ull* w1 = (const ull*)(wbase + (size_t)r1 * K);
                const ull* w2 = (const ull*)(wbase + (size_t)r2 * K);
                const ull* w3 = (const ull*)(wbase + (size_t)r3 * K);
                ull a0A = 0, a0B = 0, a1A = 0, a1B = 0;
                ull a2A = 0, a2B = 0, a3A = 0, a3B = 0;
                const float* hb = hx + 2 * lane;
                #pragma unroll 2
                for (int p = 0; p < NP; p += 4) {
                    ull h0 = *(const ull*)(hb + (p + 0) * 66);
                    ull h1 = *(const ull*)(hb + (p + 1) * 66);
                    ull h2 = *(const ull*)(hb + (p + 2) * 66);
                    ull h3 = *(const ull*)(hb + (p + 3) * 66);
                    ulonglong2 wA0 = *(const ulonglong2*)(w0 + p);
                    ulonglong2 wB0 = *(const ulonglong2*)(w0 + p + 2);
                    ulonglong2 wA1 = *(const ulonglong2*)(w1 + p);
                    ulonglong2 wB1 = *(const ulonglong2*)(w1 + p + 2);
                    ulonglong2 wA2 = *(const ulonglong2*)(w2 + p);
                    ulonglong2 wB2 = *(const ulonglong2*)(w2 + p + 2);
                    ulonglong2 wA3 = *(const ulonglong2*)(w3 + p);
                    ulonglong2 wB3 = *(const ulonglong2*)(w3 + p + 2);
                    a0A = ffma2(h0, wA0.x, a0A); a0B = ffma2(h1, wA0.y, a0B);
                    a1A = ffma2(h0, wA1.x, a1A); a1B = ffma2(h1, wA1.y, a1B);
                    a2A = ffma2(h0, wA2.x, a2A); a2B = ffma2(h1, wA2.y, a2B);
                    a3A = ffma2(h0, wA3.x, a3A); a3B = ffma2(h1, wA3.y, a3B);
                    a0A = ffma2(h2, wB0.x, a0A); a0B = ffma2(h3, wB0.y, a0B);
                    a1A = ffma2(h2, wB1.x, a1A); a1B = ffma2(h3, wB1.y, a1B);
                    a2A = ffma2(h2, wB2.x, a2A); a2B = ffma2(h3, wB2.y, a2B);
                    a3A = ffma2(h2, wB3.x, a3A); a3B = ffma2(h3, wB3.y, a3B);
                }
                float i0 = (layer == 0) ? xprow[r0] : bbase[r0];
                float i1 = (layer == 0) ? xprow[r1] : bbase[r1];
                float i2 = (layer == 0) ? xprow[r2] : bbase[r2];
                float i3 = (layer == 0) ? xprow[r3] : bbase[r3];
                ms[c0 * 32 + lane] = i0 + pairsum(a0A) + pairsum(a0B);
                if (cg + 1 < ncols) ms[c1 * 32 + lane] = i1 + pairsum(a1A) + pairsum(a1B);
                if (cg + 2 < ncols) ms[c2 * 32 + lane] = i2 + pairsum(a2A) + pairsum(a2B);
                if (cg + 3 < ncols) ms[c3 * 32 + lane] = i3 + pairsum(a3A) + pairsum(a3B);
            }
            __syncthreads();

            // ---- activation + state update ----
            float* hout = g_h + (((size_t)layer * Tsz + t) * Bsz) * Hsz;
            float* cout = g_c + (((size_t)layer * Tsz + t) * Bsz) * Hsz;
            const float* cprev = (t > 0) ? g_c + (((size_t)layer * Tsz + (t - 1)) * Bsz) * Hsz : nullptr;
            if (layer == 0) {
                for (int it = tid; it < nj * 32; it += NTHR) {
                    int b = it / nj, jj = it - (it / nj) * nj;
                    int j = j0 + jj;
                    float i_ = ms[(0 * nj + jj) * 32 + b];
                    float f_ = ms[(1 * nj + jj) * 32 + b];
                    float gg = ms[(2 * nj + jj) * 32 + b];
                    float o_ = ms[(3 * nj + jj) * 32 + b];
                    float cp = cprev ? __ldcg(cprev + (size_t)b * Hsz + j) : 0.0f;
                    float cv = sigf(i_) * tanhf(gg) + sigf(f_) * cp;
                    float hv = sigf(o_) * tanhf(cv);
                    hout[(size_t)b * Hsz + j] = hv;
                    cout[(size_t)b * Hsz + j] = cv;
                }
            } else {
                const float* clow = g_c + (((size_t)(layer - 1) * Tsz + t) * Bsz) * Hsz;
                for (int it = tid; it < nj * 32; it += NTHR) {
                    int b = it / nj, jj = it - (it / nj) * nj;
                    int j = j0 + jj;
                    float i_ = ms[(0 * nj + jj) * 32 + b];
                    float fp = ms[(1 * nj + jj) * 32 + b];
                    float fl = ms[(2 * nj + jj) * 32 + b];
                    float u_ = ms[(3 * nj + jj) * 32 + b];
                    float o_ = ms[(4 * nj + jj) * 32 + b];
                    float cp = cprev ? __ldcg(cprev + (size_t)b * Hsz + j) : 0.0f;
                    float cl = __ldcg(clow + (size_t)b * Hsz + j);
                    float cv = cp * sigf(fp + 1.0f) + cl * sigf(fl + 1.0f) + tanhf(u_) * sigf(i_);
                    float hv = sigf(o_) * tanhf(cv);
                    hout[(size_t)b * Hsz + j] = hv;
                    cout[(size_t)b * Hsz + j] = cv;
                    if (layer == 3) {
                        out[(size_t)b * Tsz * Hsz + (size_t)t * Hsz + j] = hv;
                        out[BTHn + (size_t)b * Tsz * Hsz + (size_t)t * Hsz + j] = cv;
                        if (t == Tsz - 1) {
                            out[2 * BTHn + (size_t)b * Hsz + j] = hv;
                            out[2 * BTHn + (size_t)Bsz * Hsz + (size_t)b * Hsz + j] = cv;
                        }
                    }
                }
            }
        }

        // ---- grid barrier (monotonic counter) ----
        __syncthreads();
        __threadfence();
        if (tid == 0) {
            atomicAdd(&g_bar, 1u);
            const unsigned tgt = (unsigned)NCTA * (unsigned)(s + 1);
            volatile unsigned* p = &g_bar;
            while (*p < tgt) { }
            __threadfence();
        }
        __syncthreads();
    }
}

extern "C" void kernel_launch(void* const* d_in, const int* in_sizes, int n_in,
                              void* d_out, int out_size)
{
    const float* x    = (const float*)d_in[0];
    const float* w_ih = (const float*)d_in[1];
    const float* w_hh = (const float*)d_in[2];
    const float* b_ih = (const float*)d_in[3];
    const float* b_hh = (const float*)d_in[4];
    const float* ca_w = (const float*)d_in[5];
    const float* ca_b = (const float*)d_in[6];
    float* out = (float*)d_out;

    (void)in_sizes; (void)n_in; (void)out_size;

    k_init<<<1, 32>>>();

    dim3 g(G4 / 64, (Tsz * Bsz) / 64);
    k_xproj<<<g, 256>>>(x, w_ih, b_ih, b_hh);

    const int smem_bytes = (512 * 66 + 128 * 32) * (int)sizeof(float);  // 151552
    cudaFuncSetAttribute(k_wave, cudaFuncAttributeMaxDynamicSharedMemorySize, smem_bytes);
    k_wave<<<NCTA, NTHR, smem_bytes>>>(w_hh, ca_w, ca_b, out);
}

// round 5
// speedup vs baseline: 3.3753x; 2.1513x over previous
#include <cuda_runtime.h>
#include <cstdint>
#include <math.h>

#define Bsz 32
#define Tsz 512
#define DIsz 512
#define Hsz 512
#define G4 2048
#define G5 2560
#define NCTA 148
#define NTHR 512
#define BTHn ((size_t)32*512*512)

typedef unsigned long long ull;

// ---- static device scratch; h/c layout [layer][t][j][b] (b fastest) ----
static __device__ float g_h[(size_t)4*512*512*32];
static __device__ float g_c[(size_t)4*512*512*32];
static __device__ float g_xt[(size_t)512*2048*32];          // [t][rowp][b]
static __device__ float g_wt0[(size_t)16*512*128];          // L0: [cta][k][slot]
static __device__ float g_wtca[(size_t)3*44*1024*64];       // CA: [l][cta][k][slot]
static __device__ unsigned g_bar;

__device__ __forceinline__ float sigf(float x) { return 1.0f / (1.0f + __expf(-x)); }
__device__ __forceinline__ ull ffma2(ull a, ull b, ull c) {
    ull d; asm("fma.rn.f32x2 %0, %1, %2, %3;" : "=l"(d) : "l"(a), "l"(b), "l"(c)); return d;
}
__device__ __forceinline__ ull addf2(ull a, ull b) {
    ull d; asm("add.rn.f32x2 %0, %1, %2;" : "=l"(d) : "l"(a), "l"(b)); return d;
}
__device__ __forceinline__ ull splat(float w) {
    ull d; asm("mov.b64 %0, {%1, %1};" : "=l"(d) : "f"(w)); return d;
}
__device__ __forceinline__ void unpack2(ull a, float& lo, float& hi) {
    asm("mov.b64 {%0, %1}, %2;" : "=f"(lo), "=f"(hi) : "l"(a));
}

static __device__ __host__ __forceinline__ void cta_params(int ci, int& nj, int& j0) {
    if (ci < 28) { nj = 12; j0 = ci * 12; }
    else         { nj = 11; j0 = 336 + (ci - 28) * 11; }
}

// ---------------- one-time weight transpose + barrier reset ----------------
__global__ void __launch_bounds__(256) k_fill(const float* __restrict__ w_hh,
                                              const float* __restrict__ ca_w)
{
    size_t stride = (size_t)gridDim.x * blockDim.x;
    size_t i0 = (size_t)blockIdx.x * blockDim.x + threadIdx.x;
    if (i0 == 0) g_bar = 0u;
    const size_t N0 = (size_t)16 * 512 * 128;
    for (size_t e = i0; e < N0; e += stride) {
        int s = (int)(e & 127), k = (int)((e >> 7) & 511), c = (int)(e >> 16);
        int g = s >> 5, jj = s & 31;
        g_wt0[e] = w_hh[(size_t)(g * 512 + c * 32 + jj) * 512 + k];
    }
    const size_t NC = (size_t)3 * 44 * 1024 * 64;
    for (size_t e = i0; e < NC; e += stride) {
        int s = (int)(e & 63), k = (int)((e >> 6) & 1023);
        int lc = (int)(e >> 16), c = lc % 44, l = lc / 44;
        int nj, j0; cta_params(c, nj, j0);
        float v = 0.0f;
        if (s < 5 * nj) {
            int g = s / nj, jj = s - g * nj;
            v = ca_w[((size_t)l * G5 + g * 512 + j0 + jj) * 1024 + k];
        }
        g_wtca[e] = v;
    }
}

// ---------------- xproj = x @ w_ih.T + bias, stored [t][rowp][b] ----------------
__global__ void __launch_bounds__(256) k_xproj(
    const float* __restrict__ x, const float* __restrict__ w_ih,
    const float* __restrict__ b_ih, const float* __restrict__ b_hh)
{
    __shared__ float As[16][65];
    __shared__ float Bs[16][65];
    const int bm = blockIdx.y * 64, bn = blockIdx.x * 64;
    const int tid = threadIdx.x;
    const int tr = (tid >> 4) << 2, tc = (tid & 15) << 2;
    float acc[4][4] = {};
    for (int k0 = 0; k0 < DIsz; k0 += 16) {
        #pragma unroll
        for (int i0 = 0; i0 < 4; i0++) {
            int i = i0 * 256 + tid;
            int mm = i >> 4, kk = i & 15;
            int m = bm + mm, tt = m >> 5, bb = m & 31;
            As[kk][mm] = x[((size_t)bb * Tsz + tt) * DIsz + (k0 + kk)];
            Bs[kk][mm] = w_ih[(size_t)(bn + mm) * DIsz + (k0 + kk)];
        }
        __syncthreads();
        #pragma unroll
        for (int kk = 0; kk < 16; kk++) {
            float a[4] = {As[kk][tr], As[kk][tr+1], As[kk][tr+2], As[kk][tr+3]};
            float b[4] = {Bs[kk][tc], Bs[kk][tc+1], Bs[kk][tc+2], Bs[kk][tc+3]};
            #pragma unroll
            for (int i = 0; i < 4; i++)
                #pragma unroll
                for (int j = 0; j < 4; j++)
                    acc[i][j] = fmaf(a[i], b[j], acc[i][j]);
        }
        __syncthreads();
    }
    #pragma unroll
    for (int i = 0; i < 4; i++) {
        int m = bm + tr + i, tt = m >> 5, bb = m & 31;
        #pragma unroll
        for (int j = 0; j < 4; j++) {
            int n = bn + tc + j;
            int g = n >> 9, cd = (n >> 5) & 15, jj = n & 31;
            g_xt[((size_t)tt * 2048 + cd * 128 + g * 32 + jj) * 32 + bb]
                = acc[i][j] + b_ih[n] + b_hh[n];
        }
    }
}

// ---------------- persistent wavefront LSTM, 8x8 register tiles ----------------
__global__ void __launch_bounds__(NTHR, 1) k_wave(
    const float* __restrict__ ca_b, float* __restrict__ out)
{
    extern __shared__ float sm[];
    ull*   part = (ull*)sm;                 // 16 warps * 32 lanes * 33 ull
    float* ms   = sm + (16 * 32 * 33 * 2);  // 128*32 floats

    const int tid  = threadIdx.x;
    const int lane = tid & 31;
    const int wid  = tid >> 5;
    const int cta  = blockIdx.x;
    const int r8   = lane >> 2;   // row octet 0..7
    const int b8   = lane & 3;    // batch octet 0..3

    int layer, j0, nj, ci = 0;
    if (cta < 16) { layer = 0; nj = 32; j0 = cta * 32; }
    else {
        int r = cta - 16;
        layer = 1 + r / 44;
        ci = r % 44;
        cta_params(ci, nj, j0);
    }

    for (int s = 0; s < Tsz + 3; ++s) {
        const int t = s - layer;
        if (t >= 0 && t < Tsz) {
            const int passes = (layer == 0) ? 2 : 1;
            for (int p = 0; p < passes; ++p) {
                ull acc[32];
                #pragma unroll
                for (int i = 0; i < 32; i++) acc[i] = 0ull;

                bool skip = (t == 0) && (layer == 0 || wid >= 8);
                if (!skip) {
                    int nk, wstr;
                    const float *wsrc, *hsrc;
                    if (layer == 0) {
                        nk = 32; wstr = 128;
                        int k0 = wid * 32;
                        wsrc = g_wt0 + ((size_t)cta * 512 + k0) * 128 + p * 64 + r8 * 8;
                        hsrc = g_h + (((size_t)(t - 1)) * Hsz + k0) * 32;
                    } else {
                        nk = 64; wstr = 64;
                        int k0 = wid * 64;
                        wsrc = g_wtca + (((size_t)(layer - 1) * 44 + ci) * 1024 + k0) * 64 + r8 * 8;
                        if (wid < 8)
                            hsrc = g_h + (((size_t)(layer - 1) * Tsz + t) * Hsz + k0) * 32;
                        else
                            hsrc = g_h + (((size_t)layer * Tsz + (t - 1)) * Hsz + (k0 - 512)) * 32;
                    }
                    const float* hptr = hsrc + b8 * 8;
                    #pragma unroll 2
                    for (int kk = 0; kk < nk; ++kk) {
                        float4 w0 = __ldg((const float4*)(wsrc + (size_t)kk * wstr));
                        float4 w1 = __ldg((const float4*)(wsrc + (size_t)kk * wstr + 4));
                        ulonglong2 hA = __ldcg((const ulonglong2*)(hptr + kk * 32));
                        ulonglong2 hB = __ldcg((const ulonglong2*)(hptr + kk * 32 + 4));
                        #define ROWF(W, R) { ull ws = splat(W); \
                            acc[(R)*4+0] = ffma2(hA.x, ws, acc[(R)*4+0]); \
                            acc[(R)*4+1] = ffma2(hA.y, ws, acc[(R)*4+1]); \
                            acc[(R)*4+2] = ffma2(hB.x, ws, acc[(R)*4+2]); \
                            acc[(R)*4+3] = ffma2(hB.y, ws, acc[(R)*4+3]); }
                        ROWF(w0.x, 0) ROWF(w0.y, 1) ROWF(w0.z, 2) ROWF(w0.w, 3)
                        ROWF(w1.x, 4) ROWF(w1.y, 5) ROWF(w1.z, 6) ROWF(w1.w, 7)
                        #undef ROWF
                    }
                }
                {
                    ull* myp = part + (size_t)wid * (32 * 33) + (size_t)lane * 33;
                    #pragma unroll
                    for (int i = 0; i < 32; i++) myp[i] = acc[i];
                }
                __syncthreads();

                // reduce 16 warp-partials + base -> ms[slot][b]
                for (int o = tid; o < 1024; o += NTHR) {
                    int r = o >> 4, bp = o & 15;
                    int lsrc = (r >> 3) * 4 + (bp >> 2);
                    int idx  = (r & 7) * 4 + (bp & 3);
                    ull ssum = 0ull;
                    #pragma unroll
                    for (int w = 0; w < 16; w++)
                        ssum = addf2(ssum, part[(size_t)w * (32 * 33) + (size_t)lsrc * 33 + idx]);
                    float lo, hi; unpack2(ssum, lo, hi);
                    int slot = p * 64 + r;
                    if (layer == 0) {
                        const float* xb = g_xt + ((size_t)t * 2048 + cta * 128 + slot) * 32 + 2 * bp;
                        lo += xb[0]; hi += xb[1];
                    } else if (r < 5 * nj) {
                        int g = r / nj, jj = r - g * nj;
                        float bb = ca_b[(size_t)(layer - 1) * G5 + g * 512 + j0 + jj];
                        lo += bb; hi += bb;
                    }
                    ms[slot * 32 + 2 * bp]     = lo;
                    ms[slot * 32 + 2 * bp + 1] = hi;
                }
                __syncthreads();
            }

            // activation + state update (state layout [j][b])
            float* hout = g_h + (((size_t)layer * Tsz + t) * Hsz) * 32;
            float* cout = g_c + (((size_t)layer * Tsz + t) * Hsz) * 32;
            const float* cprev = (t > 0) ? g_c + (((size_t)layer * Tsz + (t - 1)) * Hsz) * 32 : nullptr;
            if (layer == 0) {
                for (int it = tid; it < 32 * 32; it += NTHR) {
                    int jj = it >> 5, b = it & 31, j = j0 + jj;
                    float i_ = ms[(0 * 32 + jj) * 32 + b];
                    float f_ = ms[(1 * 32 + jj) * 32 + b];
                    float gg = ms[(2 * 32 + jj) * 32 + b];
                    float o_ = ms[(3 * 32 + jj) * 32 + b];
                    float cp = cprev ? __ldcg(cprev + (size_t)j * 32 + b) : 0.0f;
                    float cv = sigf(i_) * tanhf(gg) + sigf(f_) * cp;
                    float hv = sigf(o_) * tanhf(cv);
                    hout[(size_t)j * 32 + b] = hv;
                    cout[(size_t)j * 32 + b] = cv;
                }
            } else {
                const float* clow = g_c + (((size_t)(layer - 1) * Tsz + t) * Hsz) * 32;
                for (int it = tid; it < nj * 32; it += NTHR) {
                    int jj = it >> 5, b = it & 31, j = j0 + jj;
                    float i_ = ms[(0 * nj + jj) * 32 + b];
                    float fp = ms[(1 * nj + jj) * 32 + b];
                    float fl = ms[(2 * nj + jj) * 32 + b];
                    float u_ = ms[(3 * nj + jj) * 32 + b];
                    float o_ = ms[(4 * nj + jj) * 32 + b];
                    float cp = cprev ? __ldcg(cprev + (size_t)j * 32 + b) : 0.0f;
                    float cl = __ldcg(clow + (size_t)j * 32 + b);
                    float cv = cp * sigf(fp + 1.0f) + cl * sigf(fl + 1.0f) + tanhf(u_) * sigf(i_);
                    float hv = sigf(o_) * tanhf(cv);
                    hout[(size_t)j * 32 + b] = hv;
                    cout[(size_t)j * 32 + b] = cv;
                    if (layer == 3) {
                        out[(size_t)b * Tsz * Hsz + (size_t)t * Hsz + j] = hv;
                        out[BTHn + (size_t)b * Tsz * Hsz + (size_t)t * Hsz + j] = cv;
                        if (t == Tsz - 1) {
                            out[2 * BTHn + (size_t)b * Hsz + j] = hv;
                            out[2 * BTHn + (size_t)Bsz * Hsz + (size_t)b * Hsz + j] = cv;
                        }
                    }
                }
            }
        }

        // grid barrier (monotonic counter)
        __syncthreads();
        __threadfence();
        if (tid == 0) {
            atomicAdd(&g_bar, 1u);
            const unsigned tgt = (unsigned)NCTA * (unsigned)(s + 1);
            volatile unsigned* pb = &g_bar;
            while (*pb < tgt) { }
            __threadfence();
        }
        __syncthreads();
    }
}

extern "C" void kernel_launch(void* const* d_in, const int* in_sizes, int n_in,
                              void* d_out, int out_size)
{
    const float* x    = (const float*)d_in[0];
    const float* w_ih = (const float*)d_in[1];
    const float* w_hh = (const float*)d_in[2];
    const float* b_ih = (const float*)d_in[3];
    const float* b_hh = (const float*)d_in[4];
    const float* ca_w = (const float*)d_in[5];
    const float* ca_b = (const float*)d_in[6];
    float* out = (float*)d_out;
    (void)in_sizes; (void)n_in; (void)out_size;

    k_fill<<<296, 256>>>(w_hh, ca_w);

    dim3 g(G4 / 64, (Tsz * Bsz) / 64);
    k_xproj<<<g, 256>>>(x, w_ih, b_ih, b_hh);

    const int smem_bytes = 16 * 32 * 33 * 8 + 128 * 32 * 4;  // 151552
    cudaFuncSetAttribute(k_wave, cudaFuncAttributeMaxDynamicSharedMemorySize, smem_bytes);
    k_wave<<<NCTA, NTHR, smem_bytes>>>(ca_b, out);
}

// round 6
// speedup vs baseline: 5.3411x; 1.5824x over previous
#include <cuda_runtime.h>
#include <cuda_bf16.h>
#include <cstdint>
#include <math.h>

#define Bsz 32
#define Tsz 512
#define DIsz 512
#define Hsz 512
#define G4 2048
#define G5 2560
#define NCTA 148
#define NTHR 512
#define BTHn ((size_t)32*512*512)

typedef unsigned int uint;
typedef unsigned short ushort;

// ---- static device scratch ----
// h stored as bf16 hi/lo, layout [layer][t][b][k]; c fp32 [layer][t][b][j]
static __device__ __align__(16) ushort g_hhi[(size_t)4*512*32*512];
static __device__ __align__(16) ushort g_hlo[(size_t)4*512*32*512];
static __device__ float g_c[(size_t)4*512*32*512];
static __device__ float g_xt[(size_t)512*2048*32];           // [t][rowp][b]
// weights pre-packed in mma-fragment order (bf16x2 per uint)
static __device__ __align__(16) uint g_wA0[(size_t)16*16*32*128];    // L0
static __device__ __align__(16) uint g_wAca[(size_t)132*16*32*128];  // CA
static __device__ unsigned g_bar;

#define PSTR 4224            // 128*33 floats per kw partial region
#define PART_OFF 132096      // bytes: B region = 32*1032*2B*2

__device__ __forceinline__ float sigf(float x) { return 1.0f / (1.0f + __expf(-x)); }

__device__ __forceinline__ ushort bfhi(float w) {
    return __bfloat16_as_ushort(__float2bfloat16(w));
}
__device__ __forceinline__ ushort bflo(float w) {
    float h = __bfloat162float(__float2bfloat16(w));
    return __bfloat16_as_ushort(__float2bfloat16(w - h));
}

__device__ __forceinline__ void mma_bf16(float* d, const uint4& a, uint b0, uint b1) {
    asm volatile(
        "mma.sync.aligned.m16n8k16.row.col.f32.bf16.bf16.f32 "
        "{%0,%1,%2,%3},{%4,%5,%6,%7},{%8,%9},{%0,%1,%2,%3};"
        : "+f"(d[0]), "+f"(d[1]), "+f"(d[2]), "+f"(d[3])
        : "r"(a.x), "r"(a.y), "r"(a.z), "r"(a.w), "r"(b0), "r"(b1));
}

static __device__ __host__ __forceinline__ void cta_params(int ci, int& nj, int& j0) {
    if (ci < 28) { nj = 12; j0 = ci * 12; }
    else         { nj = 11; j0 = 336 + (ci - 28) * 11; }
}

// ---------------- weight fragment packing + barrier reset ----------------
__global__ void __launch_bounds__(256) k_fill(const float* __restrict__ w_hh,
                                              const float* __restrict__ ca_w)
{
    size_t stride = (size_t)gridDim.x * blockDim.x;
    size_t i0 = (size_t)blockIdx.x * blockDim.x + threadIdx.x;
    if (i0 == 0) g_bar = 0u;

    // L0: e = ((cta*16+wid)*32 + f)*128 + lane*4 + reg ; f = (ks*2+mt)*2+part
    const size_t N0 = (size_t)16*16*32*128;
    for (size_t e = i0; e < N0; e += stride) {
        int reg = (int)(e & 3), lane = (int)((e >> 2) & 31), f = (int)((e >> 7) & 31);
        int wid = (int)((e >> 12) & 15), cta = (int)(e >> 16);
        int part = f & 1, mt = (f >> 1) & 1, ks = f >> 2;
        int mw = wid >> 2, kw = wid & 3;
        int gr = lane >> 2, c0 = (lane & 3) * 2;
        int slot = mw * 32 + mt * 16 + gr + (reg & 1) * 8;
        int kk = kw * 128 + ks * 16 + c0 + ((reg >> 1) & 1) * 8;
        int row = (slot >> 5) * 512 + cta * 32 + (slot & 31);
        float w0 = w_hh[(size_t)row * 512 + kk];
        float w1 = w_hh[(size_t)row * 512 + kk + 1];
        ushort u0 = part ? bflo(w0) : bfhi(w0);
        ushort u1 = part ? bflo(w1) : bfhi(w1);
        g_wA0[e] = (uint)u0 | ((uint)u1 << 16);
    }
    // CA: e = ((lc*16+wid)*32 + f)*128 + lane*4 + reg ; f = ks*2+part
    const size_t NC = (size_t)132*16*32*128;
    for (size_t e = i0; e < NC; e += stride) {
        int reg = (int)(e & 3), lane = (int)((e >> 2) & 31), f = (int)((e >> 7) & 31);
        int wid = (int)((e >> 12) & 15), lc = (int)(e >> 16);
        int part = f & 1, ks = f >> 1;
        int mw = wid >> 2, kw = wid & 3;
        int gr = lane >> 2, c0 = (lane & 3) * 2;
        int slot = mw * 16 + gr + (reg & 1) * 8;
        int kk = kw * 256 + ks * 16 + c0 + ((reg >> 1) & 1) * 8;
        int ci = lc % 44, l = lc / 44;
        int nj, j0; cta_params(ci, nj, j0);
        float w0 = 0.0f, w1 = 0.0f;
        if (slot < 5 * nj) {
            int g = slot / nj, jj = slot - g * nj;
            int row = g * 512 + j0 + jj;
            w0 = ca_w[((size_t)l * G5 + row) * 1024 + kk];
            w1 = ca_w[((size_t)l * G5 + row) * 1024 + kk + 1];
        }
        ushort u0 = part ? bflo(w0) : bfhi(w0);
        ushort u1 = part ? bflo(w1) : bfhi(w1);
        g_wAca[e] = (uint)u0 | ((uint)u1 << 16);
    }
}

// ---------------- xproj = x @ w_ih.T + bias, stored [t][rowp][b] ----------------
__global__ void __launch_bounds__(256) k_xproj(
    const float* __restrict__ x, const float* __restrict__ w_ih,
    const float* __restrict__ b_ih, const float* __restrict__ b_hh)
{
    __shared__ float As[16][65];
    __shared__ float Bs[16][65];
    const int bm = blockIdx.y * 64, bn = blockIdx.x * 64;
    const int tid = threadIdx.x;
    const int tr = (tid >> 4) << 2, tc = (tid & 15) << 2;
    float acc[4][4] = {};
    for (int k0 = 0; k0 < DIsz; k0 += 16) {
        #pragma unroll
        for (int i0 = 0; i0 < 4; i0++) {
            int i = i0 * 256 + tid;
            int mm = i >> 4, kk = i & 15;
            int m = bm + mm, tt = m >> 5, bb = m & 31;
            As[kk][mm] = x[((size_t)bb * Tsz + tt) * DIsz + (k0 + kk)];
            Bs[kk][mm] = w_ih[(size_t)(bn + mm) * DIsz + (k0 + kk)];
        }
        __syncthreads();
        #pragma unroll
        for (int kk = 0; kk < 16; kk++) {
            float a[4] = {As[kk][tr], As[kk][tr+1], As[kk][tr+2], As[kk][tr+3]};
            float b[4] = {Bs[kk][tc], Bs[kk][tc+1], Bs[kk][tc+2], Bs[kk][tc+3]};
            #pragma unroll
            for (int i = 0; i < 4; i++)
                #pragma unroll
                for (int j = 0; j < 4; j++)
                    acc[i][j] = fmaf(a[i], b[j], acc[i][j]);
        }
        __syncthreads();
    }
    #pragma unroll
    for (int i = 0; i < 4; i++) {
        int m = bm + tr + i, tt = m >> 5, bb = m & 31;
        #pragma unroll
        for (int j = 0; j < 4; j++) {
            int n = bn + tc + j;
            int g = n >> 9, cd = (n >> 5) & 15, jj = n & 31;
            g_xt[((size_t)tt * 2048 + cd * 128 + g * 32 + jj) * 32 + bb]
                = acc[i][j] + b_ih[n] + b_hh[n];
        }
    }
}

// ---------------- persistent wavefront LSTM, bf16x2 tensor-core GEMM ----------------
__global__ void __launch_bounds__(NTHR, 1) k_wave(
    const float* __restrict__ ca_b, float* __restrict__ out)
{
    extern __shared__ char smx[];

    const int tid  = threadIdx.x;
    const int lane = tid & 31;
    const int wid  = tid >> 5;
    const int cta  = blockIdx.x;
    const int mw = wid >> 2, kw = wid & 3;
    const int gr = lane >> 2, c0 = (lane & 3) * 2;

    int layer, j0, nj, ci = 0;
    if (cta < 16) { layer = 0; nj = 32; j0 = cta * 32; }
    else {
        int r = cta - 16;
        layer = 1 + r / 44;
        ci = r % 44;
        cta_params(ci, nj, j0);
    }
    const int K  = (layer == 0) ? 512 : 1024;
    const int rs = K + 8;
    ushort* Bh = (ushort*)smx;
    ushort* Bl = Bh + 32 * rs;
    float* part = (float*)(smx + PART_OFF);

    const uint4* wp4;
    if (layer == 0)
        wp4 = (const uint4*)g_wA0 + ((size_t)(cta * 16 + wid)) * 1024 + lane;
    else
        wp4 = (const uint4*)g_wAca + ((size_t)(((layer - 1) * 44 + ci) * 16 + wid)) * 1024 + lane;

    const int nch = K >> 3;            // uint4 chunks per B row (pow2: 64/128)
    const int chsh = (layer == 0) ? 6 : 7;

    for (int s = 0; s < Tsz + 3; ++s) {
        const int t = s - layer;
        if (t >= 0 && t < Tsz) {
            // ---- stage H hi/lo into smem [b][k] (pad rs) ----
            const uint4 zz = make_uint4(0, 0, 0, 0);
            for (int e = tid; e < 32 * nch; e += NTHR) {
                int b = e >> chsh, c = e & (nch - 1);
                int k8 = c * 8;
                const ushort *sh = nullptr, *sl = nullptr;
                if (layer == 0) {
                    if (t > 0) {
                        size_t o = (((size_t)0 * Tsz + (t - 1)) * 32 + b) * 512 + k8;
                        sh = g_hhi + o; sl = g_hlo + o;
                    }
                } else {
                    if (k8 < 512) {
                        size_t o = (((size_t)(layer - 1) * Tsz + t) * 32 + b) * 512 + k8;
                        sh = g_hhi + o; sl = g_hlo + o;
                    } else if (t > 0) {
                        size_t o = (((size_t)layer * Tsz + (t - 1)) * 32 + b) * 512 + (k8 - 512);
                        sh = g_hhi + o; sl = g_hlo + o;
                    }
                }
                uint4 vh = sh ? __ldcg((const uint4*)sh) : zz;
                uint4 vl = sl ? __ldcg((const uint4*)sl) : zz;
                *(uint4*)(Bh + b * rs + k8) = vh;
                *(uint4*)(Bl + b * rs + k8) = vl;
            }
            __syncthreads();

            // ---- tensor-core GEMM ----
            if (layer == 0) {
                float d[8][4] = {};
                const int kb = kw * 128 + c0;
                #pragma unroll
                for (int ks = 0; ks < 8; ks++) {
                    uint4 ah0 = __ldg(wp4 + ((ks * 2 + 0) * 2 + 0) * 32);
                    uint4 al0 = __ldg(wp4 + ((ks * 2 + 0) * 2 + 1) * 32);
                    uint4 ah1 = __ldg(wp4 + ((ks * 2 + 1) * 2 + 0) * 32);
                    uint4 al1 = __ldg(wp4 + ((ks * 2 + 1) * 2 + 1) * 32);
                    int k = kb + ks * 16;
                    #pragma unroll
                    for (int nt = 0; nt < 4; nt++) {
                        const ushort* ph = Bh + (nt * 8 + gr) * rs + k;
                        const ushort* pl = Bl + (nt * 8 + gr) * rs + k;
                        uint bh0 = *(const uint*)ph, bh1 = *(const uint*)(ph + 8);
                        uint bl0 = *(const uint*)pl, bl1 = *(const uint*)(pl + 8);
                        mma_bf16(d[nt],     ah0, bh0, bh1);
                        mma_bf16(d[nt],     ah0, bl0, bl1);
                        mma_bf16(d[nt],     al0, bh0, bh1);
                        mma_bf16(d[4 + nt], ah1, bh0, bh1);
                        mma_bf16(d[4 + nt], ah1, bl0, bl1);
                        mma_bf16(d[4 + nt], al1, bh0, bh1);
                    }
                }
                float* pp = part + kw * PSTR;
                #pragma unroll
                for (int mt = 0; mt < 2; mt++)
                    #pragma unroll
                    for (int nt = 0; nt < 4; nt++) {
                        int sl0 = mw * 32 + mt * 16 + gr;
                        int bc = nt * 8 + c0;
                        float* dd = d[mt * 4 + nt];
                        pp[sl0 * 33 + bc] = dd[0];       pp[sl0 * 33 + bc + 1] = dd[1];
                        pp[(sl0 + 8) * 33 + bc] = dd[2]; pp[(sl0 + 8) * 33 + bc + 1] = dd[3];
                    }
            } else {
                float d[4][4] = {};
                const int kb = kw * 256 + c0;
                #pragma unroll 4
                for (int ks = 0; ks < 16; ks++) {
                    uint4 ah = __ldg(wp4 + (ks * 2 + 0) * 32);
                    uint4 al = __ldg(wp4 + (ks * 2 + 1) * 32);
                    int k = kb + ks * 16;
                    #pragma unroll
                    for (int nt = 0; nt < 4; nt++) {
                        const ushort* ph = Bh + (nt * 8 + gr) * rs + k;
                        const ushort* pl = Bl + (nt * 8 + gr) * rs + k;
                        uint bh0 = *(const uint*)ph, bh1 = *(const uint*)(ph + 8);
                        uint bl0 = *(const uint*)pl, bl1 = *(const uint*)(pl + 8);
                        mma_bf16(d[nt], ah, bh0, bh1);
                        mma_bf16(d[nt], ah, bl0, bl1);
                        mma_bf16(d[nt], al, bh0, bh1);
                    }
                }
                float* pp = part + kw * PSTR;
                #pragma unroll
                for (int nt = 0; nt < 4; nt++) {
                    int sl0 = mw * 16 + gr;
                    int bc = nt * 8 + c0;
                    pp[sl0 * 33 + bc] = d[nt][0];       pp[sl0 * 33 + bc + 1] = d[nt][1];
                    pp[(sl0 + 8) * 33 + bc] = d[nt][2]; pp[(sl0 + 8) * 33 + bc + 1] = d[nt][3];
                }
            }
            __syncthreads();

            // ---- reduce 4 kw-partials + base ----
            const int NS = (layer == 0) ? 128 : 64;
            for (int o = tid; o < NS * 32; o += NTHR) {
                int sl0 = o >> 5, b = o & 31;
                float v = part[sl0 * 33 + b] + part[PSTR + sl0 * 33 + b]
                        + part[2 * PSTR + sl0 * 33 + b] + part[3 * PSTR + sl0 * 33 + b];
                if (layer == 0) {
                    v += __ldcg(&g_xt[((size_t)t * 2048 + cta * 128 + sl0) * 32 + b]);
                } else if (sl0 < 5 * nj) {
                    v += ca_b[(size_t)(layer - 1) * G5 + (sl0 / nj) * 512 + j0 + (sl0 % nj)];
                }
                part[sl0 * 33 + b] = v;
            }
            __syncthreads();

            // ---- activation + state update ----
            float* msb = part;
            size_t so = (((size_t)layer * Tsz + t)) * 32;
            float*  cout = g_c   + so * 512;
            ushort* hho  = g_hhi + so * 512;
            ushort* hlo_ = g_hlo + so * 512;
            const float* cprev = (t > 0) ? g_c + (((size_t)layer * Tsz + (t - 1)) * 32) * 512 : nullptr;
            if (layer == 0) {
                for (int it = tid; it < 1024; it += NTHR) {
                    int b = it >> 5, jj = it & 31;
                    int j = cta * 32 + jj;
                    float i_ = msb[(0 * 32 + jj) * 33 + b];
                    float f_ = msb[(1 * 32 + jj) * 33 + b];
                    float gg = msb[(2 * 32 + jj) * 33 + b];
                    float o_ = msb[(3 * 32 + jj) * 33 + b];
                    float cp = cprev ? __ldcg(cprev + (size_t)b * 512 + j) : 0.0f;
                    float cv = sigf(i_) * tanhf(gg) + sigf(f_) * cp;
                    float hv = sigf(o_) * tanhf(cv);
                    cout[(size_t)b * 512 + j] = cv;
                    ushort uh = bfhi(hv);
                    hho[(size_t)b * 512 + j]  = uh;
                    float hf = __bfloat162float(__ushort_as_bfloat16(uh));
                    hlo_[(size_t)b * 512 + j] = bfhi(hv - hf);
                }
            } else {
                const float* clow = g_c + (((size_t)(layer - 1) * Tsz + t) * 32) * 512;
                for (int it = tid; it < nj * 32; it += NTHR) {
                    int b = it / nj, jj = it - b * nj;
                    int j = j0 + jj;
                    float i_ = msb[(0 * nj + jj) * 33 + b];
                    float fp = msb[(1 * nj + jj) * 33 + b];
                    float fl = msb[(2 * nj + jj) * 33 + b];
                    float u_ = msb[(3 * nj + jj) * 33 + b];
                    float o_ = msb[(4 * nj + jj) * 33 + b];
                    float cp = cprev ? __ldcg(cprev + (size_t)b * 512 + j) : 0.0f;
                    float cl = __ldcg(clow + (size_t)b * 512 + j);
                    float cv = cp * sigf(fp + 1.0f) + cl * sigf(fl + 1.0f) + tanhf(u_) * sigf(i_);
                    float hv = sigf(o_) * tanhf(cv);
                    cout[(size_t)b * 512 + j] = cv;
                    ushort uh = bfhi(hv);
                    hho[(size_t)b * 512 + j]  = uh;
                    float hf = __bfloat162float(__ushort_as_bfloat16(uh));
                    hlo_[(size_t)b * 512 + j] = bfhi(hv - hf);
                    if (layer == 3) {
                        out[(size_t)b * Tsz * Hsz + (size_t)t * Hsz + j] = hv;
                        out[BTHn + (size_t)b * Tsz * Hsz + (size_t)t * Hsz + j] = cv;
                        if (t == Tsz - 1) {
                            out[2 * BTHn + (size_t)b * Hsz + j] = hv;
                            out[2 * BTHn + (size_t)Bsz * Hsz + (size_t)b * Hsz + j] = cv;
                        }
                    }
                }
            }
        }

        // ---- grid barrier ----
        __syncthreads();
        __threadfence();
        if (tid == 0) {
            atomicAdd(&g_bar, 1u);
            const unsigned tgt = (unsigned)NCTA * (unsigned)(s + 1);
            volatile unsigned* pb = &g_bar;
            while (*pb < tgt) { }
            __threadfence();
        }
        __syncthreads();
    }
}

extern "C" void kernel_launch(void* const* d_in, const int* in_sizes, int n_in,
                              void* d_out, int out_size)
{
    const float* x    = (const float*)d_in[0];
    const float* w_ih = (const float*)d_in[1];
    const float* w_hh = (const float*)d_in[2];
    const float* b_ih = (const float*)d_in[3];
    const float* b_hh = (const float*)d_in[4];
    const float* ca_w = (const float*)d_in[5];
    const float* ca_b = (const float*)d_in[6];
    float* out = (float*)d_out;
    (void)in_sizes; (void)n_in; (void)out_size;

    k_fill<<<296, 256>>>(w_hh, ca_w);

    dim3 g(G4 / 64, (Tsz * Bsz) / 64);
    k_xproj<<<g, 256>>>(x, w_ih, b_ih, b_hh);

    const int smem_bytes = PART_OFF + 4 * PSTR * 4;  // 132096 + 67584 = 199680
    cudaFuncSetAttribute(k_wave, cudaFuncAttributeMaxDynamicSharedMemorySize, smem_bytes);
    k_wave<<<NCTA, NTHR, smem_bytes>>>(ca_b, out);
}

// round 7
// speedup vs baseline: 5.9092x; 1.1064x over previous
#include <cuda_runtime.h>
#include <cuda_bf16.h>
#include <cstdint>
#include <math.h>

#define Bsz 32
#define Tsz 512
#define DIsz 512
#define Hsz 512
#define G4 2048
#define G5 2560
#define NCTA 148
#define NTHR 512
#define BTHn ((size_t)32*512*512)

typedef unsigned int uint;
typedef unsigned short ushort;

// ---- static device scratch ----
static __device__ __align__(16) ushort g_hhi[(size_t)4*512*32*512];
static __device__ __align__(16) ushort g_hlo[(size_t)4*512*32*512];
static __device__ float g_c[(size_t)4*512*32*512];
static __device__ float g_xt[(size_t)512*2048*32];           // [t][rowp][b]
static __device__ __align__(16) uint g_wA0[(size_t)16*16*32*128];    // L0 frags
static __device__ __align__(16) uint g_wAca[(size_t)132*16*32*128];  // CA frags
static __device__ unsigned g_done[4];                        // per-layer step counters

#define PSTR 4224            // 128*33 floats per kw partial region
#define PART_OFF 132096      // bytes: B region = 32*1032*2B*2

__device__ __forceinline__ float sigf(float x) { return 1.0f / (1.0f + __expf(-x)); }

__device__ __forceinline__ ushort bfhi(float w) {
    return __bfloat16_as_ushort(__float2bfloat16(w));
}
__device__ __forceinline__ ushort bflo(float w) {
    float h = __bfloat162float(__float2bfloat16(w));
    return __bfloat16_as_ushort(__float2bfloat16(w - h));
}

__device__ __forceinline__ void mma_bf16(float* d, const uint4& a, uint b0, uint b1) {
    asm volatile(
        "mma.sync.aligned.m16n8k16.row.col.f32.bf16.bf16.f32 "
        "{%0,%1,%2,%3},{%4,%5,%6,%7},{%8,%9},{%0,%1,%2,%3};"
        : "+f"(d[0]), "+f"(d[1]), "+f"(d[2]), "+f"(d[3])
        : "r"(a.x), "r"(a.y), "r"(a.z), "r"(a.w), "r"(b0), "r"(b1));
}

static __device__ __host__ __forceinline__ void cta_params(int ci, int& nj, int& j0) {
    if (ci < 28) { nj = 12; j0 = ci * 12; }
    else         { nj = 11; j0 = 336 + (ci - 28) * 11; }
}

// ---------------- weight fragment packing + counter reset ----------------
__global__ void __launch_bounds__(256) k_fill(const float* __restrict__ w_hh,
                                              const float* __restrict__ ca_w)
{
    size_t stride = (size_t)gridDim.x * blockDim.x;
    size_t i0 = (size_t)blockIdx.x * blockDim.x + threadIdx.x;
    if (i0 < 4) g_done[i0] = 0u;

    const size_t N0 = (size_t)16*16*32*128;
    for (size_t e = i0; e < N0; e += stride) {
        int reg = (int)(e & 3), lane = (int)((e >> 2) & 31), f = (int)((e >> 7) & 31);
        int wid = (int)((e >> 12) & 15), cta = (int)(e >> 16);
        int part = f & 1, mt = (f >> 1) & 1, ks = f >> 2;
        int mw = wid >> 2, kw = wid & 3;
        int gr = lane >> 2, c0 = (lane & 3) * 2;
        int slot = mw * 32 + mt * 16 + gr + (reg & 1) * 8;
        int kk = kw * 128 + ks * 16 + c0 + ((reg >> 1) & 1) * 8;
        int row = (slot >> 5) * 512 + cta * 32 + (slot & 31);
        float w0 = w_hh[(size_t)row * 512 + kk];
        float w1 = w_hh[(size_t)row * 512 + kk + 1];
        ushort u0 = part ? bflo(w0) : bfhi(w0);
        ushort u1 = part ? bflo(w1) : bfhi(w1);
        g_wA0[e] = (uint)u0 | ((uint)u1 << 16);
    }
    const size_t NC = (size_t)132*16*32*128;
    for (size_t e = i0; e < NC; e += stride) {
        int reg = (int)(e & 3), lane = (int)((e >> 2) & 31), f = (int)((e >> 7) & 31);
        int wid = (int)((e >> 12) & 15), lc = (int)(e >> 16);
        int part = f & 1, ks = f >> 1;
        int mw = wid >> 2, kw = wid & 3;
        int gr = lane >> 2, c0 = (lane & 3) * 2;
        int slot = mw * 16 + gr + (reg & 1) * 8;
        int kk = kw * 256 + ks * 16 + c0 + ((reg >> 1) & 1) * 8;
        int ci = lc % 44, l = lc / 44;
        int nj, j0; cta_params(ci, nj, j0);
        float w0 = 0.0f, w1 = 0.0f;
        if (slot < 5 * nj) {
            int g = slot / nj, jj = slot - g * nj;
            int row = g * 512 + j0 + jj;
            w0 = ca_w[((size_t)l * G5 + row) * 1024 + kk];
            w1 = ca_w[((size_t)l * G5 + row) * 1024 + kk + 1];
        }
        ushort u0 = part ? bflo(w0) : bfhi(w0);
        ushort u1 = part ? bflo(w1) : bfhi(w1);
        g_wAca[e] = (uint)u0 | ((uint)u1 << 16);
    }
}

// ---------------- xproj = x @ w_ih.T + bias, stored [t][rowp][b] ----------------
__global__ void __launch_bounds__(256) k_xproj(
    const float* __restrict__ x, const float* __restrict__ w_ih,
    const float* __restrict__ b_ih, const float* __restrict__ b_hh)
{
    __shared__ float As[16][65];
    __shared__ float Bs[16][65];
    const int bm = blockIdx.y * 64, bn = blockIdx.x * 64;
    const int tid = threadIdx.x;
    const int tr = (tid >> 4) << 2, tc = (tid & 15) << 2;
    float acc[4][4] = {};
    for (int k0 = 0; k0 < DIsz; k0 += 16) {
        #pragma unroll
        for (int i0 = 0; i0 < 4; i0++) {
            int i = i0 * 256 + tid;
            int mm = i >> 4, kk = i & 15;
            int m = bm + mm, tt = m >> 5, bb = m & 31;
            As[kk][mm] = x[((size_t)bb * Tsz + tt) * DIsz + (k0 + kk)];
            Bs[kk][mm] = w_ih[(size_t)(bn + mm) * DIsz + (k0 + kk)];
        }
        __syncthreads();
        #pragma unroll
        for (int kk = 0; kk < 16; kk++) {
            float a[4] = {As[kk][tr], As[kk][tr+1], As[kk][tr+2], As[kk][tr+3]};
            float b[4] = {Bs[kk][tc], Bs[kk][tc+1], Bs[kk][tc+2], Bs[kk][tc+3]};
            #pragma unroll
            for (int i = 0; i < 4; i++)
                #pragma unroll
                for (int j = 0; j < 4; j++)
                    acc[i][j] = fmaf(a[i], b[j], acc[i][j]);
        }
        __syncthreads();
    }
    #pragma unroll
    for (int i = 0; i < 4; i++) {
        int m = bm + tr + i, tt = m >> 5, bb = m & 31;
        #pragma unroll
        for (int j = 0; j < 4; j++) {
            int n = bn + tc + j;
            int g = n >> 9, cd = (n >> 5) & 15, jj = n & 31;
            g_xt[((size_t)tt * 2048 + cd * 128 + g * 32 + jj) * 32 + bb]
                = acc[i][j] + b_ih[n] + b_hh[n];
        }
    }
}

// ---------------- persistent self-timed LSTM, bf16x2 tensor-core GEMM ----------------
__global__ void __launch_bounds__(NTHR, 1) k_wave(
    const float* __restrict__ ca_b, float* __restrict__ out)
{
    extern __shared__ char smx[];

    const int tid  = threadIdx.x;
    const int lane = tid & 31;
    const int wid  = tid >> 5;
    const int cta  = blockIdx.x;
    const int mw = wid >> 2, kw = wid & 3;
    const int gr = lane >> 2, c0 = (lane & 3) * 2;

    int layer, j0, nj, ci = 0;
    if (cta < 16) { layer = 0; nj = 32; j0 = cta * 32; }
    else {
        int r = cta - 16;
        layer = 1 + r / 44;
        ci = r % 44;
        cta_params(ci, nj, j0);
    }
    const int K  = (layer == 0) ? 512 : 1024;
    const int rs = K + 8;
    ushort* Bh = (ushort*)smx;
    ushort* Bl = Bh + 32 * rs;
    float* part = (float*)(smx + PART_OFF);

    const uint4* wp4;
    if (layer == 0)
        wp4 = (const uint4*)g_wA0 + ((size_t)(cta * 16 + wid)) * 1024 + lane;
    else
        wp4 = (const uint4*)g_wAca + ((size_t)(((layer - 1) * 44 + ci) * 16 + wid)) * 1024 + lane;

    const int nch = K >> 3;
    const int chsh = (layer == 0) ? 6 : 7;

    for (int t = 0; t < Tsz; ++t) {
        // ---- wait for producers (self-timed, per-layer counters) ----
        if (tid == 0) {
            if (layer == 0) {
                if (t > 0) {
                    volatile unsigned* p = &g_done[0];
                    while (*p < 16u * (unsigned)t) { }
                }
            } else {
                unsigned needl = (layer == 1 ? 16u : 44u) * (unsigned)(t + 1);
                volatile unsigned* pl = &g_done[layer - 1];
                while (*pl < needl) { }
                if (t > 0) {
                    volatile unsigned* po = &g_done[layer];
                    while (*po < 44u * (unsigned)t) { }
                }
            }
            __threadfence();
        }
        __syncthreads();

        // ---- stage H hi/lo into smem [b][k] ----
        {
            const uint4 zz = make_uint4(0, 0, 0, 0);
            for (int e = tid; e < 32 * nch; e += NTHR) {
                int b = e >> chsh, c = e & (nch - 1);
                int k8 = c * 8;
                const ushort *sh = nullptr, *sl = nullptr;
                if (layer == 0) {
                    if (t > 0) {
                        size_t o = (((size_t)(t - 1)) * 32 + b) * 512 + k8;
                        sh = g_hhi + o; sl = g_hlo + o;
                    }
                } else {
                    if (k8 < 512) {
                        size_t o = (((size_t)(layer - 1) * Tsz + t) * 32 + b) * 512 + k8;
                        sh = g_hhi + o; sl = g_hlo + o;
                    } else if (t > 0) {
                        size_t o = (((size_t)layer * Tsz + (t - 1)) * 32 + b) * 512 + (k8 - 512);
                        sh = g_hhi + o; sl = g_hlo + o;
                    }
                }
                uint4 vh = sh ? __ldcg((const uint4*)sh) : zz;
                uint4 vl = sl ? __ldcg((const uint4*)sl) : zz;
                *(uint4*)(Bh + b * rs + k8) = vh;
                *(uint4*)(Bl + b * rs + k8) = vl;
            }
        }
        __syncthreads();

        // ---- tensor-core GEMM -> partials ----
        if (layer == 0) {
            float d[8][4] = {};
            const int kb = kw * 128 + c0;
            #pragma unroll
            for (int ks = 0; ks < 8; ks++) {
                uint4 ah0 = __ldg(wp4 + ((ks * 2 + 0) * 2 + 0) * 32);
                uint4 al0 = __ldg(wp4 + ((ks * 2 + 0) * 2 + 1) * 32);
                uint4 ah1 = __ldg(wp4 + ((ks * 2 + 1) * 2 + 0) * 32);
                uint4 al1 = __ldg(wp4 + ((ks * 2 + 1) * 2 + 1) * 32);
                int k = kb + ks * 16;
                #pragma unroll
                for (int nt = 0; nt < 4; nt++) {
                    const ushort* ph = Bh + (nt * 8 + gr) * rs + k;
                    const ushort* pl = Bl + (nt * 8 + gr) * rs + k;
                    uint bh0 = *(const uint*)ph, bh1 = *(const uint*)(ph + 8);
                    uint bl0 = *(const uint*)pl, bl1 = *(const uint*)(pl + 8);
                    mma_bf16(d[nt],     ah0, bh0, bh1);
                    mma_bf16(d[nt],     ah0, bl0, bl1);
                    mma_bf16(d[nt],     al0, bh0, bh1);
                    mma_bf16(d[4 + nt], ah1, bh0, bh1);
                    mma_bf16(d[4 + nt], ah1, bl0, bl1);
                    mma_bf16(d[4 + nt], al1, bh0, bh1);
                }
            }
            float* pp = part + kw * PSTR;
            #pragma unroll
            for (int mt = 0; mt < 2; mt++)
                #pragma unroll
                for (int nt = 0; nt < 4; nt++) {
                    int sl0 = mw * 32 + mt * 16 + gr;
                    int bc = nt * 8 + c0;
                    float* dd = d[mt * 4 + nt];
                    pp[sl0 * 33 + bc] = dd[0];       pp[sl0 * 33 + bc + 1] = dd[1];
                    pp[(sl0 + 8) * 33 + bc] = dd[2]; pp[(sl0 + 8) * 33 + bc + 1] = dd[3];
                }
        } else {
            float d[4][4] = {};
            const int kb = kw * 256 + c0;
            #pragma unroll 4
            for (int ks = 0; ks < 16; ks++) {
                uint4 ah = __ldg(wp4 + (ks * 2 + 0) * 32);
                uint4 al = __ldg(wp4 + (ks * 2 + 1) * 32);
                int k = kb + ks * 16;
                #pragma unroll
                for (int nt = 0; nt < 4; nt++) {
                    const ushort* ph = Bh + (nt * 8 + gr) * rs + k;
                    const ushort* pl = Bl + (nt * 8 + gr) * rs + k;
                    uint bh0 = *(const uint*)ph, bh1 = *(const uint*)(ph + 8);
                    uint bl0 = *(const uint*)pl, bl1 = *(const uint*)(pl + 8);
                    mma_bf16(d[nt], ah, bh0, bh1);
                    mma_bf16(d[nt], ah, bl0, bl1);
                    mma_bf16(d[nt], al, bh0, bh1);
                }
            }
            float* pp = part + kw * PSTR;
            #pragma unroll
            for (int nt = 0; nt < 4; nt++) {
                int sl0 = mw * 16 + gr;
                int bc = nt * 8 + c0;
                pp[sl0 * 33 + bc] = d[nt][0];       pp[sl0 * 33 + bc + 1] = d[nt][1];
                pp[(sl0 + 8) * 33 + bc] = d[nt][2]; pp[(sl0 + 8) * 33 + bc + 1] = d[nt][3];
            }
        }
        __syncthreads();

        // ---- merged reduce + activation + state update ----
        {
            size_t so = (((size_t)layer * Tsz + t)) * 32;
            float*  cout = g_c   + so * 512;
            ushort* hho  = g_hhi + so * 512;
            ushort* hlo_ = g_hlo + so * 512;
            const float* cprev = (t > 0) ? g_c + (((size_t)layer * Tsz + (t - 1)) * 32) * 512 : nullptr;
            #define RED(SL, B) (part[(SL) * 33 + (B)] + part[PSTR + (SL) * 33 + (B)] \
                              + part[2 * PSTR + (SL) * 33 + (B)] + part[3 * PSTR + (SL) * 33 + (B)])
            if (layer == 0) {
                const float* xb = g_xt + ((size_t)t * 2048 + cta * 128) * 32;
                for (int it = tid; it < 1024; it += NTHR) {
                    int b = it >> 5, jj = it & 31;
                    int j = cta * 32 + jj;
                    float i_ = RED(0 * 32 + jj, b) + __ldcg(xb + (0 * 32 + jj) * 32 + b);
                    float f_ = RED(1 * 32 + jj, b) + __ldcg(xb + (1 * 32 + jj) * 32 + b);
                    float gg = RED(2 * 32 + jj, b) + __ldcg(xb + (2 * 32 + jj) * 32 + b);
                    float o_ = RED(3 * 32 + jj, b) + __ldcg(xb + (3 * 32 + jj) * 32 + b);
                    float cp = cprev ? __ldcg(cprev + (size_t)b * 512 + j) : 0.0f;
                    float cv = sigf(i_) * tanhf(gg) + sigf(f_) * cp;
                    float hv = sigf(o_) * tanhf(cv);
                    cout[(size_t)b * 512 + j] = cv;
                    ushort uh = bfhi(hv);
                    hho[(size_t)b * 512 + j]  = uh;
                    float hf = __bfloat162float(__ushort_as_bfloat16(uh));
                    hlo_[(size_t)b * 512 + j] = bfhi(hv - hf);
                }
            } else {
                const float* clow = g_c + (((size_t)(layer - 1) * Tsz + t) * 32) * 512;
                const float* cb = ca_b + (size_t)(layer - 1) * G5;
                for (int it = tid; it < nj * 32; it += NTHR) {
                    int b = it / nj, jj = it - b * nj;
                    int j = j0 + jj;
                    float i_ = RED(0 * nj + jj, b) + cb[0 * 512 + j];
                    float fp = RED(1 * nj + jj, b) + cb[1 * 512 + j];
                    float fl = RED(2 * nj + jj, b) + cb[2 * 512 + j];
                    float u_ = RED(3 * nj + jj, b) + cb[3 * 512 + j];
                    float o_ = RED(4 * nj + jj, b) + cb[4 * 512 + j];
                    float cp = cprev ? __ldcg(cprev + (size_t)b * 512 + j) : 0.0f;
                    float cl = __ldcg(clow + (size_t)b * 512 + j);
                    float cv = cp * sigf(fp + 1.0f) + cl * sigf(fl + 1.0f) + tanhf(u_) * sigf(i_);
                    float hv = sigf(o_) * tanhf(cv);
                    cout[(size_t)b * 512 + j] = cv;
                    ushort uh = bfhi(hv);
                    hho[(size_t)b * 512 + j]  = uh;
                    float hf = __bfloat162float(__ushort_as_bfloat16(uh));
                    hlo_[(size_t)b * 512 + j] = bfhi(hv - hf);
                    if (layer == 3) {
                        out[(size_t)b * Tsz * Hsz + (size_t)t * Hsz + j] = hv;
                        out[BTHn + (size_t)b * Tsz * Hsz + (size_t)t * Hsz + j] = cv;
                        if (t == Tsz - 1) {
                            out[2 * BTHn + (size_t)b * Hsz + j] = hv;
                            out[2 * BTHn + (size_t)Bsz * Hsz + (size_t)b * Hsz + j] = cv;
                        }
                    }
                }
            }
            #undef RED
        }
        __syncthreads();

        // ---- publish completion of step t ----
        if (tid == 0) {
            __threadfence();
            atomicAdd(&g_done[layer], 1u);
        }
    }
}

extern "C" void kernel_launch(void* const* d_in, const int* in_sizes, int n_in,
                              void* d_out, int out_size)
{
    const float* x    = (const float*)d_in[0];
    const float* w_ih = (const float*)d_in[1];
    const float* w_hh = (const float*)d_in[2];
    const float* b_ih = (const float*)d_in[3];
    const float* b_hh = (const float*)d_in[4];
    const float* ca_w = (const float*)d_in[5];
    const float* ca_b = (const float*)d_in[6];
    float* out = (float*)d_out;
    (void)in_sizes; (void)n_in; (void)out_size;

    k_fill<<<296, 256>>>(w_hh, ca_w);

    dim3 g(G4 / 64, (Tsz * Bsz) / 64);
    k_xproj<<<g, 256>>>(x, w_ih, b_ih, b_hh);

    const int smem_bytes = PART_OFF + 4 * PSTR * 4;  // 199680
    cudaFuncSetAttribute(k_wave, cudaFuncAttributeMaxDynamicSharedMemorySize, smem_bytes);
    k_wave<<<NCTA, NTHR, smem_bytes>>>(ca_b, out);
}